// round 1
// baseline (speedup 1.0000x reference)
#include <cuda_runtime.h>
#include <math.h>

// Problem constants: B=4096 (derived), T=64, C=128, H=64
#define TT 64
#define CC 128
#define HH 64

typedef unsigned long long ull;

// ---- packed f32x2 helpers (Blackwell sm_103a) ----
__device__ __forceinline__ ull pk2(float lo, float hi) {
    ull r; asm("mov.b64 %0,{%1,%2};" : "=l"(r) : "f"(lo), "f"(hi)); return r;
}
__device__ __forceinline__ float2 upk2(ull v) {
    float2 f; asm("mov.b64 {%0,%1},%2;" : "=f"(f.x), "=f"(f.y) : "l"(v)); return f;
}
__device__ __forceinline__ ull fma2(ull a, ull b, ull c) {
    ull d; asm("fma.rn.f32x2 %0,%1,%2,%3;" : "=l"(d) : "l"(a), "l"(b), "l"(c)); return d;
}

// smem layout (floats). Strides padded to dodge bank conflicts.
#define WS_LD 196   // W tile: 128 x 192 (Wq|Wk|Wv), stride 196
#define XS_LD 132   // X tile: 64 x 128, stride 132
#define QLD   66    // q / kT / v / p: 64 x 64, stride 66

#define WS_OFF 0
#define XS_OFF 25088                 // 128*196
#define Q_OFF  (XS_OFF + 8448)       // 64*132 -> 33536
#define KT_OFF (Q_OFF + 4224)        // 64*66  -> 37760
#define V_OFF  (KT_OFF + 4224)       // 41984
#define SMEM_FLOATS (V_OFF + 4224)   // 46208 floats = 184832 bytes
#define SMEM_BYTES (SMEM_FLOATS * 4)
// scores p aliases the W region (W dead after phase 1; 64*66=4224 <= 25088)

__global__ void __launch_bounds__(256, 1)
DiqqetBashi_attn_kernel(const float* __restrict__ x,
                        const float* __restrict__ Wq,
                        const float* __restrict__ Wk,
                        const float* __restrict__ Wv,
                        float* __restrict__ out) {
    extern __shared__ float sm[];
    float* ws = sm + WS_OFF;
    float* xs = sm + XS_OFF;
    float* q  = sm + Q_OFF;
    float* kT = sm + KT_OFF;
    float* v  = sm + V_OFF;
    float* p  = sm + WS_OFF;   // alias

    const int b   = blockIdx.x;
    const int tid = threadIdx.x;

    // ---- stage W = [Wq | Wk | Wv] into smem (float4) ----
    {
        const float4* wq4 = (const float4*)Wq;
        const float4* wk4 = (const float4*)Wk;
        const float4* wv4 = (const float4*)Wv;
        #pragma unroll
        for (int idx = tid; idx < 2048; idx += 256) {   // 128*64/4
            int c = idx >> 4, h4 = (idx & 15) << 2;
            *(float4*)&ws[c * WS_LD + h4]        = wq4[idx];
            *(float4*)&ws[c * WS_LD + 64 + h4]   = wk4[idx];
            *(float4*)&ws[c * WS_LD + 128 + h4]  = wv4[idx];
        }
        const float4* x4 = (const float4*)(x + (size_t)b * TT * CC);
        #pragma unroll
        for (int idx = tid; idx < 2048; idx += 256) {   // 64*128/4
            int t = idx >> 5, c4 = (idx & 31) << 2;
            *(float4*)&xs[t * XS_LD + c4] = x4[idx];
        }
    }
    __syncthreads();

    const int ty = tid >> 4;    // 0..15 (row group)
    const int tx = tid & 15;    // 0..15 (col group)
    const float SCALE = 0.088388347648318447f;  // 128^-0.5

    // ================= Phase 1: QKV = X[64,128] @ W[128,192] =================
    // thread tile: 4 rows x 12 cols, f32x2 pairs along cols
    {
        ull acc[4][6];
        #pragma unroll
        for (int i = 0; i < 4; i++)
            #pragma unroll
            for (int jp = 0; jp < 6; jp++) acc[i][jp] = 0ull;

        #pragma unroll 4
        for (int c = 0; c < CC; c++) {
            ull xx[4];
            #pragma unroll
            for (int i = 0; i < 4; i++) {
                float xv = xs[(ty * 4 + i) * XS_LD + c];
                xx[i] = pk2(xv, xv);
            }
            ull wp[6];
            #pragma unroll
            for (int jp = 0; jp < 6; jp++)
                wp[jp] = *(const ull*)&ws[c * WS_LD + tx * 12 + jp * 2];
            #pragma unroll
            for (int i = 0; i < 4; i++)
                #pragma unroll
                for (int jp = 0; jp < 6; jp++)
                    acc[i][jp] = fma2(xx[i], wp[jp], acc[i][jp]);
        }
        __syncthreads();   // done reading ws/xs before overwriting q/kT/v (& later p aliasing ws)

        // writeback: q scaled; k transposed; v direct
        #pragma unroll
        for (int i = 0; i < 4; i++) {
            int r = ty * 4 + i;
            #pragma unroll
            for (int jp = 0; jp < 6; jp++) {
                float2 f = upk2(acc[i][jp]);
                int c0 = tx * 12 + jp * 2;
                #pragma unroll
                for (int e = 0; e < 2; e++) {
                    int col = c0 + e;
                    float val = e ? f.y : f.x;
                    if (col < 64)        q[r * QLD + col] = val * SCALE;
                    else if (col < 128)  kT[(col - 64) * QLD + r] = val;
                    else                 v[r * QLD + (col - 128)] = val;
                }
            }
        }
    }
    __syncthreads();

    // ================= Phase 2: S = q[64,64] @ kT[64,64]  (causal later) =====
    {
        ull acc2[4][2];
        #pragma unroll
        for (int i = 0; i < 4; i++) { acc2[i][0] = 0ull; acc2[i][1] = 0ull; }

        #pragma unroll 4
        for (int h = 0; h < HH; h++) {
            ull qq[4];
            #pragma unroll
            for (int i = 0; i < 4; i++) {
                float qv = q[(ty * 4 + i) * QLD + h];
                qq[i] = pk2(qv, qv);
            }
            ull kp[2];
            #pragma unroll
            for (int jp = 0; jp < 2; jp++)
                kp[jp] = *(const ull*)&kT[h * QLD + tx * 4 + jp * 2];
            #pragma unroll
            for (int i = 0; i < 4; i++)
                #pragma unroll
                for (int jp = 0; jp < 2; jp++)
                    acc2[i][jp] = fma2(qq[i], kp[jp], acc2[i][jp]);
        }
        #pragma unroll
        for (int i = 0; i < 4; i++) {
            int r = ty * 4 + i;
            #pragma unroll
            for (int jp = 0; jp < 2; jp++) {
                float2 f = upk2(acc2[i][jp]);
                p[r * QLD + tx * 4 + jp * 2]     = f.x;
                p[r * QLD + tx * 4 + jp * 2 + 1] = f.y;
            }
        }
    }
    __syncthreads();

    // ================= Causal softmax over rows of p =================
    {
        const int row = tid >> 2, part = tid & 3;   // 4 threads per row
        float* pr = p + row * QLD + part * 16;
        float ev[16];
        float m = -1e30f;
        #pragma unroll
        for (int t = 0; t < 16; t++) {
            int col = part * 16 + t;
            float sv = (col <= row) ? pr[t] : -1e30f;
            ev[t] = sv;
            m = fmaxf(m, sv);
        }
        m = fmaxf(m, __shfl_xor_sync(0xffffffffu, m, 1));
        m = fmaxf(m, __shfl_xor_sync(0xffffffffu, m, 2));
        float s = 0.f;
        #pragma unroll
        for (int t = 0; t < 16; t++) {
            int col = part * 16 + t;
            float e = (col <= row) ? __expf(ev[t] - m) : 0.f;
            ev[t] = e;
            s += e;
        }
        s += __shfl_xor_sync(0xffffffffu, s, 1);
        s += __shfl_xor_sync(0xffffffffu, s, 2);
        float inv = __frcp_rn(s);
        #pragma unroll
        for (int t = 0; t < 16; t++) pr[t] = ev[t] * inv;
    }
    __syncthreads();

    // ================= Phase 3: O = P[64,64] @ V[64,64] =================
    {
        ull acc3[4][2];
        #pragma unroll
        for (int i = 0; i < 4; i++) { acc3[i][0] = 0ull; acc3[i][1] = 0ull; }

        #pragma unroll 4
        for (int s = 0; s < TT; s++) {
            ull pp[4];
            #pragma unroll
            for (int i = 0; i < 4; i++) {
                float pv = p[(ty * 4 + i) * QLD + s];
                pp[i] = pk2(pv, pv);
            }
            ull vp[2];
            #pragma unroll
            for (int jp = 0; jp < 2; jp++)
                vp[jp] = *(const ull*)&v[s * QLD + tx * 4 + jp * 2];
            #pragma unroll
            for (int i = 0; i < 4; i++)
                #pragma unroll
                for (int jp = 0; jp < 2; jp++)
                    acc3[i][jp] = fma2(pp[i], vp[jp], acc3[i][jp]);
        }

        float* ob = out + (size_t)b * TT * HH;
        #pragma unroll
        for (int i = 0; i < 4; i++) {
            int r = ty * 4 + i;
            float2 a0 = upk2(acc3[i][0]);
            float2 a1 = upk2(acc3[i][1]);
            float4 o = make_float4(a0.x, a0.y, a1.x, a1.y);
            *(float4*)&ob[r * HH + tx * 4] = o;
        }
    }
}

extern "C" void kernel_launch(void* const* d_in, const int* in_sizes, int n_in,
                              void* d_out, int out_size) {
    const float* x  = (const float*)d_in[0];
    const float* Wq = (const float*)d_in[1];
    const float* Wk = (const float*)d_in[2];
    const float* Wv = (const float*)d_in[3];
    float* out = (float*)d_out;

    int B = in_sizes[0] / (TT * CC);

    cudaFuncSetAttribute(DiqqetBashi_attn_kernel,
                         cudaFuncAttributeMaxDynamicSharedMemorySize, SMEM_BYTES);
    DiqqetBashi_attn_kernel<<<B, 256, SMEM_BYTES>>>(x, Wq, Wk, Wv, out);
}

// round 2
// speedup vs baseline: 1.0014x; 1.0014x over previous
#include <cuda_runtime.h>
#include <math.h>

// Problem constants: B=4096 (derived), T=64, C=128, H=64
#define TT 64
#define CC 128
#define HH 64

typedef unsigned long long ull;

// ---- packed f32x2 helpers (Blackwell sm_103a) ----
__device__ __forceinline__ ull pk2(float lo, float hi) {
    ull r; asm("mov.b64 %0,{%1,%2};" : "=l"(r) : "f"(lo), "f"(hi)); return r;
}
__device__ __forceinline__ float2 upk2(ull v) {
    float2 f; asm("mov.b64 {%0,%1},%2;" : "=f"(f.x), "=f"(f.y) : "l"(v)); return f;
}
__device__ __forceinline__ ull fma2(ull a, ull b, ull c) {
    ull d; asm("fma.rn.f32x2 %0,%1,%2,%3;" : "=l"(d) : "l"(a), "l"(b), "l"(c)); return d;
}

// smem layout (floats). Strides padded to dodge bank conflicts.
#define WS_LD 196   // W tile: 128 x 192 (Wq|Wk|Wv), stride 196
#define XS_LD 132   // X tile: 64 x 128, stride 132
#define QLD   66    // q / kT / v / p: 64 x 64, stride 66

#define WS_OFF 0
#define XS_OFF 25088                 // 128*196
#define Q_OFF  (XS_OFF + 8448)       // 64*132 -> 33536
#define KT_OFF (Q_OFF + 4224)        // 64*66  -> 37760
#define V_OFF  (KT_OFF + 4224)       // 41984
#define SMEM_FLOATS (V_OFF + 4224)   // 46208 floats = 184832 bytes
#define SMEM_BYTES (SMEM_FLOATS * 4)
// scores p aliases the W region (W dead after phase 1; 64*66=4224 <= 25088)

__global__ void __launch_bounds__(256, 1)
DiqqetBashi_attn_kernel(const float* __restrict__ x,
                        const float* __restrict__ Wq,
                        const float* __restrict__ Wk,
                        const float* __restrict__ Wv,
                        float* __restrict__ out) {
    extern __shared__ float sm[];
    float* ws = sm + WS_OFF;
    float* xs = sm + XS_OFF;
    float* q  = sm + Q_OFF;
    float* kT = sm + KT_OFF;
    float* v  = sm + V_OFF;
    float* p  = sm + WS_OFF;   // alias

    const int b   = blockIdx.x;
    const int tid = threadIdx.x;

    // ---- stage W = [Wq | Wk | Wv] into smem (float4) ----
    {
        const float4* wq4 = (const float4*)Wq;
        const float4* wk4 = (const float4*)Wk;
        const float4* wv4 = (const float4*)Wv;
        #pragma unroll
        for (int idx = tid; idx < 2048; idx += 256) {   // 128*64/4
            int c = idx >> 4, h4 = (idx & 15) << 2;
            *(float4*)&ws[c * WS_LD + h4]        = wq4[idx];
            *(float4*)&ws[c * WS_LD + 64 + h4]   = wk4[idx];
            *(float4*)&ws[c * WS_LD + 128 + h4]  = wv4[idx];
        }
        const float4* x4 = (const float4*)(x + (size_t)b * TT * CC);
        #pragma unroll
        for (int idx = tid; idx < 2048; idx += 256) {   // 64*128/4
            int t = idx >> 5, c4 = (idx & 31) << 2;
            *(float4*)&xs[t * XS_LD + c4] = x4[idx];
        }
    }
    __syncthreads();

    const int ty = tid >> 4;    // 0..15 (row group)
    const int tx = tid & 15;    // 0..15 (col group)
    const float SCALE = 0.088388347648318447f;  // 128^-0.5

    // ================= Phase 1: QKV = X[64,128] @ W[128,192] =================
    // thread tile: 4 rows x 12 cols, f32x2 pairs along cols
    {
        ull acc[4][6];
        #pragma unroll
        for (int i = 0; i < 4; i++)
            #pragma unroll
            for (int jp = 0; jp < 6; jp++) acc[i][jp] = 0ull;

        #pragma unroll 4
        for (int c = 0; c < CC; c++) {
            ull xx[4];
            #pragma unroll
            for (int i = 0; i < 4; i++) {
                float xv = xs[(ty * 4 + i) * XS_LD + c];
                xx[i] = pk2(xv, xv);
            }
            ull wp[6];
            #pragma unroll
            for (int jp = 0; jp < 6; jp++)
                wp[jp] = *(const ull*)&ws[c * WS_LD + tx * 12 + jp * 2];
            #pragma unroll
            for (int i = 0; i < 4; i++)
                #pragma unroll
                for (int jp = 0; jp < 6; jp++)
                    acc[i][jp] = fma2(xx[i], wp[jp], acc[i][jp]);
        }
        __syncthreads();   // done reading ws/xs before overwriting q/kT/v (& later p aliasing ws)

        // writeback: q scaled; k transposed; v direct
        #pragma unroll
        for (int i = 0; i < 4; i++) {
            int r = ty * 4 + i;
            #pragma unroll
            for (int jp = 0; jp < 6; jp++) {
                float2 f = upk2(acc[i][jp]);
                int c0 = tx * 12 + jp * 2;
                #pragma unroll
                for (int e = 0; e < 2; e++) {
                    int col = c0 + e;
                    float val = e ? f.y : f.x;
                    if (col < 64)        q[r * QLD + col] = val * SCALE;
                    else if (col < 128)  kT[(col - 64) * QLD + r] = val;
                    else                 v[r * QLD + (col - 128)] = val;
                }
            }
        }
    }
    __syncthreads();

    // ================= Phase 2: S = q[64,64] @ kT[64,64]  (causal later) =====
    {
        ull acc2[4][2];
        #pragma unroll
        for (int i = 0; i < 4; i++) { acc2[i][0] = 0ull; acc2[i][1] = 0ull; }

        #pragma unroll 4
        for (int h = 0; h < HH; h++) {
            ull qq[4];
            #pragma unroll
            for (int i = 0; i < 4; i++) {
                float qv = q[(ty * 4 + i) * QLD + h];
                qq[i] = pk2(qv, qv);
            }
            ull kp[2];
            #pragma unroll
            for (int jp = 0; jp < 2; jp++)
                kp[jp] = *(const ull*)&kT[h * QLD + tx * 4 + jp * 2];
            #pragma unroll
            for (int i = 0; i < 4; i++)
                #pragma unroll
                for (int jp = 0; jp < 2; jp++)
                    acc2[i][jp] = fma2(qq[i], kp[jp], acc2[i][jp]);
        }
        #pragma unroll
        for (int i = 0; i < 4; i++) {
            int r = ty * 4 + i;
            #pragma unroll
            for (int jp = 0; jp < 2; jp++) {
                float2 f = upk2(acc2[i][jp]);
                p[r * QLD + tx * 4 + jp * 2]     = f.x;
                p[r * QLD + tx * 4 + jp * 2 + 1] = f.y;
            }
        }
    }
    __syncthreads();

    // ================= Causal softmax over rows of p =================
    {
        const int row = tid >> 2, part = tid & 3;   // 4 threads per row
        float* pr = p + row * QLD + part * 16;
        float ev[16];
        float m = -1e30f;
        #pragma unroll
        for (int t = 0; t < 16; t++) {
            int col = part * 16 + t;
            float sv = (col <= row) ? pr[t] : -1e30f;
            ev[t] = sv;
            m = fmaxf(m, sv);
        }
        m = fmaxf(m, __shfl_xor_sync(0xffffffffu, m, 1));
        m = fmaxf(m, __shfl_xor_sync(0xffffffffu, m, 2));
        float s = 0.f;
        #pragma unroll
        for (int t = 0; t < 16; t++) {
            int col = part * 16 + t;
            float e = (col <= row) ? __expf(ev[t] - m) : 0.f;
            ev[t] = e;
            s += e;
        }
        s += __shfl_xor_sync(0xffffffffu, s, 1);
        s += __shfl_xor_sync(0xffffffffu, s, 2);
        float inv = __frcp_rn(s);
        #pragma unroll
        for (int t = 0; t < 16; t++) pr[t] = ev[t] * inv;
    }
    __syncthreads();

    // ================= Phase 3: O = P[64,64] @ V[64,64] =================
    {
        ull acc3[4][2];
        #pragma unroll
        for (int i = 0; i < 4; i++) { acc3[i][0] = 0ull; acc3[i][1] = 0ull; }

        #pragma unroll 4
        for (int s = 0; s < TT; s++) {
            ull pp[4];
            #pragma unroll
            for (int i = 0; i < 4; i++) {
                float pv = p[(ty * 4 + i) * QLD + s];
                pp[i] = pk2(pv, pv);
            }
            ull vp[2];
            #pragma unroll
            for (int jp = 0; jp < 2; jp++)
                vp[jp] = *(const ull*)&v[s * QLD + tx * 4 + jp * 2];
            #pragma unroll
            for (int i = 0; i < 4; i++)
                #pragma unroll
                for (int jp = 0; jp < 2; jp++)
                    acc3[i][jp] = fma2(pp[i], vp[jp], acc3[i][jp]);
        }

        float* ob = out + (size_t)b * TT * HH;
        #pragma unroll
        for (int i = 0; i < 4; i++) {
            int r = ty * 4 + i;
            float2 a0 = upk2(acc3[i][0]);
            float2 a1 = upk2(acc3[i][1]);
            float4 o = make_float4(a0.x, a0.y, a1.x, a1.y);
            *(float4*)&ob[r * HH + tx * 4] = o;
        }
    }
}

extern "C" void kernel_launch(void* const* d_in, const int* in_sizes, int n_in,
                              void* d_out, int out_size) {
    const float* x  = (const float*)d_in[0];
    const float* Wq = (const float*)d_in[1];
    const float* Wk = (const float*)d_in[2];
    const float* Wv = (const float*)d_in[3];
    float* out = (float*)d_out;

    int B = in_sizes[0] / (TT * CC);

    cudaFuncSetAttribute(DiqqetBashi_attn_kernel,
                         cudaFuncAttributeMaxDynamicSharedMemorySize, SMEM_BYTES);
    DiqqetBashi_attn_kernel<<<B, 256, SMEM_BYTES>>>(x, Wq, Wk, Wv, out);
}

// round 4
// speedup vs baseline: 2.0520x; 2.0492x over previous
#include <cuda_runtime.h>
#include <cuda_bf16.h>
#include <stdint.h>

#define TT 64
#define CC 128
#define HH 64
#define SCALE_Q 0.08838834764831844f   // 128^-0.5

// ---------------- smem arena (byte offsets) ----------------
// Phase 1: XH/XL [128 rows x 128 k] bf16 stride 136; WH/WL [192 n x 128 k] stride 136 (n-major)
#define XH0 0
#define XL0 34816
#define WH0 69632
#define WL0 121856
#define SMEM_BYTES 174080
#define LDX 136     // halves
#define LDW 136
#define LD2 72
// Phase 2/3 arena (aliases X/W, valid after phase-1 sync):
// arr: 0=QH 1=QL 2=KH 3=KL 4=VTH 5=VTL ; each [64 x 72] bf16 = 9216 B per batch
#define A2OFF(arr, b) ((arr) * 18432 + (b) * 9216)

// ---------------- helpers ----------------
__device__ __forceinline__ void sp2(float v0, float v1, uint32_t& H, uint32_t& L) {
    __nv_bfloat162 h = __floats2bfloat162_rn(v0, v1);   // .x = v0 (low half)
    float r0 = v0 - __bfloat162float(h.x);
    float r1 = v1 - __bfloat162float(h.y);
    __nv_bfloat162 l = __floats2bfloat162_rn(r0, r1);
    H = *(uint32_t*)&h;
    L = *(uint32_t*)&l;
}
__device__ __forceinline__ void sp1(float v, uint16_t& H, uint16_t& L) {
    __nv_bfloat16 h = __float2bfloat16(v);
    H = __bfloat16_as_ushort(h);
    L = __bfloat16_as_ushort(__float2bfloat16(v - __bfloat162float(h)));
}
__device__ __forceinline__ void mma16816(float* c,
                                         uint32_t a0, uint32_t a1, uint32_t a2, uint32_t a3,
                                         uint32_t b0, uint32_t b1) {
    asm volatile(
        "mma.sync.aligned.m16n8k16.row.col.f32.bf16.bf16.f32 "
        "{%0,%1,%2,%3}, {%4,%5,%6,%7}, {%8,%9}, {%0,%1,%2,%3};"
        : "+f"(c[0]), "+f"(c[1]), "+f"(c[2]), "+f"(c[3])
        : "r"(a0), "r"(a1), "r"(a2), "r"(a3), "r"(b0), "r"(b1));
}

// ---------------- main kernel ----------------
__global__ void __launch_bounds__(256)
DiqqetBashi_hmma_kernel(const float* __restrict__ x,
                        const float* __restrict__ Wq,
                        const float* __restrict__ Wk,
                        const float* __restrict__ Wv,
                        float* __restrict__ out) {
    extern __shared__ char sm[];
    const int tid  = threadIdx.x;
    const int wid  = tid >> 5;
    const int lane = tid & 31;
    const int qk   = lane & 3;     // quad id   -> k/col pair selector
    const int lr   = lane >> 2;    // group id  -> row / n selector
    const int b0   = blockIdx.x * 2;

    uint16_t* XH = (uint16_t*)(sm + XH0);
    uint16_t* XL = (uint16_t*)(sm + XL0);
    uint16_t* WH = (uint16_t*)(sm + WH0);
    uint16_t* WL = (uint16_t*)(sm + WL0);

    // ---- stage X (2 batches, 128 rows x 128 cols f32) -> split bf16 ----
    {
        const float4* x4 = (const float4*)(x + (size_t)b0 * TT * CC);
        #pragma unroll
        for (int it = 0; it < 16; ++it) {
            int idx = tid + it * 256;
            int r = idx >> 5, c0 = (idx & 31) << 2;
            float4 v = x4[idx];
            uint32_t h01, l01, h23, l23;
            sp2(v.x, v.y, h01, l01);
            sp2(v.z, v.w, h23, l23);
            *(unsigned long long*)&XH[r * LDX + c0] =
                (unsigned long long)h01 | ((unsigned long long)h23 << 32);
            *(unsigned long long*)&XL[r * LDX + c0] =
                (unsigned long long)l01 | ((unsigned long long)l23 << 32);
        }
    }
    // ---- stage W (n-major [n=h global][k=c]), fold scale into Wq ----
    {
        int h = tid & 63;
        int cb = tid >> 6;   // 0..3
        #pragma unroll
        for (int g = 0; g < 3; ++g) {
            const float* Wg = (g == 0) ? Wq : (g == 1) ? Wk : Wv;
            int n = g * 64 + h;
            #pragma unroll
            for (int it = 0; it < 32; ++it) {
                int c = it * 4 + cb;
                float v = Wg[c * 64 + h];
                if (g == 0) v *= SCALE_Q;
                uint16_t hb, lb; sp1(v, hb, lb);
                WH[n * LDW + c] = hb;
                WL[n * LDW + c] = lb;
            }
        }
    }
    __syncthreads();

    // ================= Phase 1: QKV[128,192] = X[128,128] @ W ================
    const int wy = wid & 3;    // 32-row block
    const int wx = wid >> 2;   // 96-col half
    float acc[2][12][4];
    #pragma unroll
    for (int m = 0; m < 2; m++)
        #pragma unroll
        for (int n = 0; n < 12; n++)
            #pragma unroll
            for (int e = 0; e < 4; e++) acc[m][n][e] = 0.f;

    const uint32_t* XH32 = (const uint32_t*)XH;
    const uint32_t* XL32 = (const uint32_t*)XL;
    const uint32_t* WH32 = (const uint32_t*)WH;
    const uint32_t* WL32 = (const uint32_t*)WL;

    #pragma unroll
    for (int kt = 0; kt < 8; ++kt) {
        uint32_t ah[2][4], al[2][4];
        #pragma unroll
        for (int mi = 0; mi < 2; ++mi) {
            int rA = wy * 32 + mi * 16 + lr;
            int ab = rA * 68 + kt * 8 + qk;
            ah[mi][0] = XH32[ab];           ah[mi][1] = XH32[ab + 8 * 68];
            ah[mi][2] = XH32[ab + 4];       ah[mi][3] = XH32[ab + 8 * 68 + 4];
            al[mi][0] = XL32[ab];           al[mi][1] = XL32[ab + 8 * 68];
            al[mi][2] = XL32[ab + 4];       al[mi][3] = XL32[ab + 8 * 68 + 4];
        }
        #pragma unroll
        for (int nt = 0; nt < 12; ++nt) {
            int n = wx * 96 + nt * 8 + lr;
            int bi = n * 68 + kt * 8 + qk;
            uint32_t bh0 = WH32[bi], bh1 = WH32[bi + 4];
            uint32_t bl0 = WL32[bi], bl1 = WL32[bi + 4];
            #pragma unroll
            for (int mi = 0; mi < 2; ++mi) {
                mma16816(acc[mi][nt], ah[mi][0], ah[mi][1], ah[mi][2], ah[mi][3], bh0, bh1);
                mma16816(acc[mi][nt], al[mi][0], al[mi][1], al[mi][2], al[mi][3], bh0, bh1);
                mma16816(acc[mi][nt], ah[mi][0], ah[mi][1], ah[mi][2], ah[mi][3], bl0, bl1);
            }
        }
    }
    __syncthreads();   // all phase-1 reads of X/W done before arena reuse

    // ---- writeback: Q,K -> [t][h] split; V -> transposed [h][t] split ----
    {
        #pragma unroll
        for (int mi = 0; mi < 2; ++mi) {
            int rA = wy * 32 + mi * 16 + lr;
            int rB = rA + 8;
            int b_ = rA >> 6;
            int tA = rA & 63, tB = rB & 63;
            #pragma unroll
            for (int nt = 0; nt < 12; ++nt) {
                int colbase = wx * 96 + nt * 8;
                int rg = colbase >> 6;          // 0=Q 1=K 2=V
                int off = colbase & 63;
                float* a = acc[mi][nt];
                if (rg < 2) {
                    uint32_t* DH = (uint32_t*)(sm + A2OFF(rg * 2, b_));
                    uint32_t* DL = (uint32_t*)(sm + A2OFF(rg * 2 + 1, b_));
                    int ci = (off >> 1) + qk;
                    uint32_t H, L;
                    sp2(a[0], a[1], H, L); DH[tA * 36 + ci] = H; DL[tA * 36 + ci] = L;
                    sp2(a[2], a[3], H, L); DH[tB * 36 + ci] = H; DL[tB * 36 + ci] = L;
                } else {
                    uint16_t* VH = (uint16_t*)(sm + A2OFF(4, b_));
                    uint16_t* VL = (uint16_t*)(sm + A2OFF(5, b_));
                    int h0 = off + qk * 2;
                    uint16_t hb, lb;
                    sp1(a[0], hb, lb); VH[h0 * LD2 + tA] = hb;       VL[h0 * LD2 + tA] = lb;
                    sp1(a[1], hb, lb); VH[(h0 + 1) * LD2 + tA] = hb; VL[(h0 + 1) * LD2 + tA] = lb;
                    sp1(a[2], hb, lb); VH[h0 * LD2 + tB] = hb;       VL[h0 * LD2 + tB] = lb;
                    sp1(a[3], hb, lb); VH[(h0 + 1) * LD2 + tB] = hb; VL[(h0 + 1) * LD2 + tB] = lb;
                }
            }
        }
    }
    __syncthreads();

    // ================= Phase 2: S = Q @ K^T (per batch, in registers) ========
    const int bb2 = wid >> 2;            // batch for phases 2/3
    const int mrow = (wid & 3) * 16;     // 16-row block within batch
    const uint32_t* QH32 = (const uint32_t*)(sm + A2OFF(0, bb2));
    const uint32_t* QL32 = (const uint32_t*)(sm + A2OFF(1, bb2));
    const uint32_t* KH32 = (const uint32_t*)(sm + A2OFF(2, bb2));
    const uint32_t* KL32 = (const uint32_t*)(sm + A2OFF(3, bb2));

    float s2[8][4];
    #pragma unroll
    for (int n = 0; n < 8; n++)
        #pragma unroll
        for (int e = 0; e < 4; e++) s2[n][e] = 0.f;

    #pragma unroll
    for (int kt = 0; kt < 4; ++kt) {
        int rA = mrow + lr;
        int ab = rA * 36 + kt * 8 + qk;
        uint32_t ah0 = QH32[ab],     ah1 = QH32[ab + 8 * 36];
        uint32_t ah2 = QH32[ab + 4], ah3 = QH32[ab + 8 * 36 + 4];
        uint32_t al0 = QL32[ab],     al1 = QL32[ab + 8 * 36];
        uint32_t al2 = QL32[ab + 4], al3 = QL32[ab + 8 * 36 + 4];
        #pragma unroll
        for (int nt = 0; nt < 8; ++nt) {
            int n = nt * 8 + lr;
            int bi = n * 36 + kt * 8 + qk;
            uint32_t bh0 = KH32[bi], bh1 = KH32[bi + 4];
            uint32_t bl0 = KL32[bi], bl1 = KL32[bi + 4];
            mma16816(s2[nt], ah0, ah1, ah2, ah3, bh0, bh1);
            mma16816(s2[nt], al0, al1, al2, al3, bh0, bh1);
            mma16816(s2[nt], ah0, ah1, ah2, ah3, bl0, bl1);
        }
    }

    // ---- causal softmax in registers (rows rowA, rowB per thread) ----
    const int rowA = mrow + lr, rowB = rowA + 8;
    {
        float mA = -1e30f, mB = -1e30f;
        #pragma unroll
        for (int nt = 0; nt < 8; ++nt) {
            int c0 = nt * 8 + qk * 2;
            s2[nt][0] = (c0     <= rowA) ? s2[nt][0] : -1e30f;
            s2[nt][1] = (c0 + 1 <= rowA) ? s2[nt][1] : -1e30f;
            s2[nt][2] = (c0     <= rowB) ? s2[nt][2] : -1e30f;
            s2[nt][3] = (c0 + 1 <= rowB) ? s2[nt][3] : -1e30f;
            mA = fmaxf(mA, fmaxf(s2[nt][0], s2[nt][1]));
            mB = fmaxf(mB, fmaxf(s2[nt][2], s2[nt][3]));
        }
        mA = fmaxf(mA, __shfl_xor_sync(0xffffffffu, mA, 1));
        mA = fmaxf(mA, __shfl_xor_sync(0xffffffffu, mA, 2));
        mB = fmaxf(mB, __shfl_xor_sync(0xffffffffu, mB, 1));
        mB = fmaxf(mB, __shfl_xor_sync(0xffffffffu, mB, 2));
        float sA = 0.f, sB = 0.f;
        #pragma unroll
        for (int nt = 0; nt < 8; ++nt) {
            int c0 = nt * 8 + qk * 2;
            float e0 = (c0     <= rowA) ? __expf(s2[nt][0] - mA) : 0.f;
            float e1 = (c0 + 1 <= rowA) ? __expf(s2[nt][1] - mA) : 0.f;
            float e2 = (c0     <= rowB) ? __expf(s2[nt][2] - mB) : 0.f;
            float e3 = (c0 + 1 <= rowB) ? __expf(s2[nt][3] - mB) : 0.f;
            s2[nt][0] = e0; s2[nt][1] = e1; s2[nt][2] = e2; s2[nt][3] = e3;
            sA += e0 + e1;  sB += e2 + e3;
        }
        sA += __shfl_xor_sync(0xffffffffu, sA, 1);
        sA += __shfl_xor_sync(0xffffffffu, sA, 2);
        sB += __shfl_xor_sync(0xffffffffu, sB, 1);
        sB += __shfl_xor_sync(0xffffffffu, sB, 2);
        float iA = __frcp_rn(sA), iB = __frcp_rn(sB);
        #pragma unroll
        for (int nt = 0; nt < 8; ++nt) {
            s2[nt][0] *= iA; s2[nt][1] *= iA;
            s2[nt][2] *= iB; s2[nt][3] *= iB;
        }
    }

    // ================= Phase 3: O = P @ V  (A fragments built in-register) ===
    const uint32_t* VH32 = (const uint32_t*)(sm + A2OFF(4, bb2));
    const uint32_t* VL32 = (const uint32_t*)(sm + A2OFF(5, bb2));
    float o[8][4];
    #pragma unroll
    for (int n = 0; n < 8; n++)
        #pragma unroll
        for (int e = 0; e < 4; e++) o[n][e] = 0.f;

    #pragma unroll
    for (int kt = 0; kt < 4; ++kt) {
        uint32_t ah0, ah1, ah2, ah3, al0, al1, al2, al3;
        sp2(s2[2 * kt][0],     s2[2 * kt][1],     ah0, al0);
        sp2(s2[2 * kt][2],     s2[2 * kt][3],     ah1, al1);
        sp2(s2[2 * kt + 1][0], s2[2 * kt + 1][1], ah2, al2);
        sp2(s2[2 * kt + 1][2], s2[2 * kt + 1][3], ah3, al3);
        #pragma unroll
        for (int nt = 0; nt < 8; ++nt) {
            int n = nt * 8 + lr;
            int bi = n * 36 + kt * 8 + qk;
            uint32_t bh0 = VH32[bi], bh1 = VH32[bi + 4];
            uint32_t bl0 = VL32[bi], bl1 = VL32[bi + 4];
            mma16816(o[nt], ah0, ah1, ah2, ah3, bh0, bh1);
            mma16816(o[nt], al0, al1, al2, al3, bh0, bh1);
            mma16816(o[nt], ah0, ah1, ah2, ah3, bl0, bl1);
        }
    }

    // ---- store O ----
    {
        float* ob = out + ((size_t)(b0 + bb2) * TT) * HH;
        #pragma unroll
        for (int nt = 0; nt < 8; ++nt) {
            int c0 = nt * 8 + qk * 2;
            *(float2*)&ob[rowA * HH + c0] = make_float2(o[nt][0], o[nt][1]);
            *(float2*)&ob[rowB * HH + c0] = make_float2(o[nt][2], o[nt][3]);
        }
    }
}

extern "C" void kernel_launch(void* const* d_in, const int* in_sizes, int n_in,
                              void* d_out, int out_size) {
    const float* x  = (const float*)d_in[0];
    const float* Wq = (const float*)d_in[1];
    const float* Wk = (const float*)d_in[2];
    const float* Wv = (const float*)d_in[3];
    float* out = (float*)d_out;

    int B = in_sizes[0] / (TT * CC);

    cudaFuncSetAttribute(DiqqetBashi_hmma_kernel,
                         cudaFuncAttributeMaxDynamicSharedMemorySize, SMEM_BYTES);
    DiqqetBashi_hmma_kernel<<<B / 2, 256, SMEM_BYTES>>>(x, Wq, Wk, Wv, out);
}

// round 5
// speedup vs baseline: 2.9941x; 1.4591x over previous
#include <cuda_runtime.h>
#include <cuda_bf16.h>
#include <stdint.h>

#define TT 64
#define CC 128
#define HH 64
#define SCALE_Q 0.08838834764831844f   // 128^-0.5

// W in fragment-ordered split form: [nt(24)][kt(8)][lane(32)] -> {bh0,bh1,bl0,bl1}
__device__ uint4 WFRAG[6144];

// ---------------- smem arena (byte offsets) ----------------
// Phase 1: XH [128 x 136 halves] @0 (34816B), XL @34816 (34816B)  -- aliased by:
// Phase 2/3: arr 0=QH 1=QL 2=KH 3=KL 4=VTH 5=VTL; each [64 x 72] bf16 per batch
#define SMEM_BYTES 110592
#define LDX 136
#define LD2 72
#define A2OFF(arr, b) ((arr) * 18432 + (b) * 9216)

// ---------------- helpers ----------------
__device__ __forceinline__ void sp2(float v0, float v1, uint32_t& H, uint32_t& L) {
    __nv_bfloat162 h = __floats2bfloat162_rn(v0, v1);
    float r0 = v0 - __bfloat162float(h.x);
    float r1 = v1 - __bfloat162float(h.y);
    __nv_bfloat162 l = __floats2bfloat162_rn(r0, r1);
    H = *(uint32_t*)&h;
    L = *(uint32_t*)&l;
}
__device__ __forceinline__ void sp1(float v, uint16_t& H, uint16_t& L) {
    __nv_bfloat16 h = __float2bfloat16(v);
    H = __bfloat16_as_ushort(h);
    L = __bfloat16_as_ushort(__float2bfloat16(v - __bfloat162float(h)));
}
__device__ __forceinline__ void mma16816(float* c,
                                         uint32_t a0, uint32_t a1, uint32_t a2, uint32_t a3,
                                         uint32_t b0, uint32_t b1) {
    asm volatile(
        "mma.sync.aligned.m16n8k16.row.col.f32.bf16.bf16.f32 "
        "{%0,%1,%2,%3}, {%4,%5,%6,%7}, {%8,%9}, {%0,%1,%2,%3};"
        : "+f"(c[0]), "+f"(c[1]), "+f"(c[2]), "+f"(c[3])
        : "r"(a0), "r"(a1), "r"(a2), "r"(a3), "r"(b0), "r"(b1));
}

// ---------------- prep kernel: W -> fragment-ordered split global ----------------
__global__ void prep_w_kernel(const float* __restrict__ Wq,
                              const float* __restrict__ Wk,
                              const float* __restrict__ Wv) {
    int i = blockIdx.x * 256 + threadIdx.x;
    if (i >= 6144) return;
    int lane = i & 31;
    int kt   = (i >> 5) & 7;
    int nt   = i >> 8;
    int qk = lane & 3, lr = lane >> 2;
    int n = nt * 8 + lr;
    int g = n >> 6, h = n & 63;
    const float* Wg = (g == 0) ? Wq : (g == 1) ? Wk : Wv;
    float s = (g == 0) ? SCALE_Q : 1.0f;
    int k0 = kt * 16 + qk * 2;
    float w0 = Wg[(k0    ) * HH + h] * s;
    float w1 = Wg[(k0 + 1) * HH + h] * s;
    float w2 = Wg[(k0 + 8) * HH + h] * s;
    float w3 = Wg[(k0 + 9) * HH + h] * s;
    uint32_t h0, l0, h1, l1;
    sp2(w0, w1, h0, l0);
    sp2(w2, w3, h1, l1);
    WFRAG[i] = make_uint4(h0, h1, l0, l1);
}

// ---------------- main kernel ----------------
__global__ void __launch_bounds__(256, 2)
DiqqetBashi_hmma2_kernel(const float* __restrict__ x,
                         float* __restrict__ out) {
    extern __shared__ char sm[];
    const int tid  = threadIdx.x;
    const int wid  = tid >> 5;
    const int lane = tid & 31;
    const int qk   = lane & 3;
    const int lr   = lane >> 2;
    const int b0   = blockIdx.x * 2;

    uint16_t* XH = (uint16_t*)sm;
    uint16_t* XL = (uint16_t*)(sm + 34816);

    // ---- stage X (2 batches = 128 rows x 128 cols f32) -> split bf16 ----
    {
        const float4* x4 = (const float4*)(x + (size_t)b0 * TT * CC);
        #pragma unroll
        for (int it = 0; it < 16; ++it) {
            int idx = tid + it * 256;
            int r = idx >> 5, c0 = (idx & 31) << 2;
            float4 v = x4[idx];
            uint32_t h01, l01, h23, l23;
            sp2(v.x, v.y, h01, l01);
            sp2(v.z, v.w, h23, l23);
            *(unsigned long long*)&XH[r * LDX + c0] =
                (unsigned long long)h01 | ((unsigned long long)h23 << 32);
            *(unsigned long long*)&XL[r * LDX + c0] =
                (unsigned long long)l01 | ((unsigned long long)l23 << 32);
        }
    }
    __syncthreads();

    // ================= Phase 1: QKV[128,192] = X[128,128] @ W ================
    // warp owns cols [wid*24, wid*24+24) (3 n-tiles), all 128 rows (8 m-tiles)
    float acc[8][3][4];
    #pragma unroll
    for (int m = 0; m < 8; m++)
        #pragma unroll
        for (int j = 0; j < 3; j++)
            #pragma unroll
            for (int e = 0; e < 4; e++) acc[m][j][e] = 0.f;

    const uint32_t* XH32 = (const uint32_t*)XH;
    const uint32_t* XL32 = (const uint32_t*)XL;

    #pragma unroll
    for (int kt = 0; kt < 8; ++kt) {
        uint4 B0 = WFRAG[((wid * 3 + 0) * 8 + kt) * 32 + lane];
        uint4 B1 = WFRAG[((wid * 3 + 1) * 8 + kt) * 32 + lane];
        uint4 B2 = WFRAG[((wid * 3 + 2) * 8 + kt) * 32 + lane];
        #pragma unroll
        for (int m = 0; m < 8; ++m) {
            int ab = (m * 16 + lr) * 68 + kt * 8 + qk;
            uint32_t ah0 = XH32[ab],     ah1 = XH32[ab + 8 * 68];
            uint32_t ah2 = XH32[ab + 4], ah3 = XH32[ab + 8 * 68 + 4];
            uint32_t al0 = XL32[ab],     al1 = XL32[ab + 8 * 68];
            uint32_t al2 = XL32[ab + 4], al3 = XL32[ab + 8 * 68 + 4];
            mma16816(acc[m][0], ah0, ah1, ah2, ah3, B0.x, B0.y);
            mma16816(acc[m][0], al0, al1, al2, al3, B0.x, B0.y);
            mma16816(acc[m][0], ah0, ah1, ah2, ah3, B0.z, B0.w);
            mma16816(acc[m][1], ah0, ah1, ah2, ah3, B1.x, B1.y);
            mma16816(acc[m][1], al0, al1, al2, al3, B1.x, B1.y);
            mma16816(acc[m][1], ah0, ah1, ah2, ah3, B1.z, B1.w);
            mma16816(acc[m][2], ah0, ah1, ah2, ah3, B2.x, B2.y);
            mma16816(acc[m][2], al0, al1, al2, al3, B2.x, B2.y);
            mma16816(acc[m][2], ah0, ah1, ah2, ah3, B2.z, B2.w);
        }
    }
    __syncthreads();   // X reads done before arena overwrite

    // ---- writeback: Q,K -> [t][h] split; V -> transposed [h][t] split ----
    #pragma unroll
    for (int m = 0; m < 8; ++m) {
        int rA = m * 16 + lr;
        int rB = rA + 8;
        int b_ = rA >> 6;
        int tA = rA & 63, tB = rB & 63;
        #pragma unroll
        for (int j = 0; j < 3; ++j) {
            int colbase = wid * 24 + j * 8;
            int rg = colbase >> 6;          // 0=Q 1=K 2=V
            int off = colbase & 63;
            float* a = acc[m][j];
            if (rg < 2) {
                uint32_t* DH = (uint32_t*)(sm + A2OFF(rg * 2, b_));
                uint32_t* DL = (uint32_t*)(sm + A2OFF(rg * 2 + 1, b_));
                int ci = (off >> 1) + qk;
                uint32_t H, L;
                sp2(a[0], a[1], H, L); DH[tA * 36 + ci] = H; DL[tA * 36 + ci] = L;
                sp2(a[2], a[3], H, L); DH[tB * 36 + ci] = H; DL[tB * 36 + ci] = L;
            } else {
                uint16_t* VH = (uint16_t*)(sm + A2OFF(4, b_));
                uint16_t* VL = (uint16_t*)(sm + A2OFF(5, b_));
                int h0 = off + qk * 2;
                uint16_t hb, lb;
                sp1(a[0], hb, lb); VH[h0 * LD2 + tA] = hb;       VL[h0 * LD2 + tA] = lb;
                sp1(a[1], hb, lb); VH[(h0 + 1) * LD2 + tA] = hb; VL[(h0 + 1) * LD2 + tA] = lb;
                sp1(a[2], hb, lb); VH[h0 * LD2 + tB] = hb;       VL[h0 * LD2 + tB] = lb;
                sp1(a[3], hb, lb); VH[(h0 + 1) * LD2 + tB] = hb; VL[(h0 + 1) * LD2 + tB] = lb;
            }
        }
    }
    __syncthreads();

    // ================= Phase 2: S = Q @ K^T (per batch, in registers) ========
    const int bb2 = wid >> 2;            // batch
    const int mrow = (wid & 3) * 16;     // 16-row block within batch
    const uint32_t* QH32 = (const uint32_t*)(sm + A2OFF(0, bb2));
    const uint32_t* QL32 = (const uint32_t*)(sm + A2OFF(1, bb2));
    const uint32_t* KH32 = (const uint32_t*)(sm + A2OFF(2, bb2));
    const uint32_t* KL32 = (const uint32_t*)(sm + A2OFF(3, bb2));

    float s2[8][4];
    #pragma unroll
    for (int n = 0; n < 8; n++)
        #pragma unroll
        for (int e = 0; e < 4; e++) s2[n][e] = 0.f;

    #pragma unroll
    for (int kt = 0; kt < 4; ++kt) {
        int rA = mrow + lr;
        int ab = rA * 36 + kt * 8 + qk;
        uint32_t ah0 = QH32[ab],     ah1 = QH32[ab + 8 * 36];
        uint32_t ah2 = QH32[ab + 4], ah3 = QH32[ab + 8 * 36 + 4];
        uint32_t al0 = QL32[ab],     al1 = QL32[ab + 8 * 36];
        uint32_t al2 = QL32[ab + 4], al3 = QL32[ab + 8 * 36 + 4];
        #pragma unroll
        for (int nt = 0; nt < 8; ++nt) {
            int n = nt * 8 + lr;
            int bi = n * 36 + kt * 8 + qk;
            uint32_t bh0 = KH32[bi], bh1 = KH32[bi + 4];
            uint32_t bl0 = KL32[bi], bl1 = KL32[bi + 4];
            mma16816(s2[nt], ah0, ah1, ah2, ah3, bh0, bh1);
            mma16816(s2[nt], al0, al1, al2, al3, bh0, bh1);
            mma16816(s2[nt], ah0, ah1, ah2, ah3, bl0, bl1);
        }
    }

    // ---- causal softmax in registers ----
    const int rowA = mrow + lr, rowB = rowA + 8;
    {
        float mA = -1e30f, mB = -1e30f;
        #pragma unroll
        for (int nt = 0; nt < 8; ++nt) {
            int c0 = nt * 8 + qk * 2;
            s2[nt][0] = (c0     <= rowA) ? s2[nt][0] : -1e30f;
            s2[nt][1] = (c0 + 1 <= rowA) ? s2[nt][1] : -1e30f;
            s2[nt][2] = (c0     <= rowB) ? s2[nt][2] : -1e30f;
            s2[nt][3] = (c0 + 1 <= rowB) ? s2[nt][3] : -1e30f;
            mA = fmaxf(mA, fmaxf(s2[nt][0], s2[nt][1]));
            mB = fmaxf(mB, fmaxf(s2[nt][2], s2[nt][3]));
        }
        mA = fmaxf(mA, __shfl_xor_sync(0xffffffffu, mA, 1));
        mA = fmaxf(mA, __shfl_xor_sync(0xffffffffu, mA, 2));
        mB = fmaxf(mB, __shfl_xor_sync(0xffffffffu, mB, 1));
        mB = fmaxf(mB, __shfl_xor_sync(0xffffffffu, mB, 2));
        float sA = 0.f, sB = 0.f;
        #pragma unroll
        for (int nt = 0; nt < 8; ++nt) {
            int c0 = nt * 8 + qk * 2;
            float e0 = (c0     <= rowA) ? __expf(s2[nt][0] - mA) : 0.f;
            float e1 = (c0 + 1 <= rowA) ? __expf(s2[nt][1] - mA) : 0.f;
            float e2 = (c0     <= rowB) ? __expf(s2[nt][2] - mB) : 0.f;
            float e3 = (c0 + 1 <= rowB) ? __expf(s2[nt][3] - mB) : 0.f;
            s2[nt][0] = e0; s2[nt][1] = e1; s2[nt][2] = e2; s2[nt][3] = e3;
            sA += e0 + e1;  sB += e2 + e3;
        }
        sA += __shfl_xor_sync(0xffffffffu, sA, 1);
        sA += __shfl_xor_sync(0xffffffffu, sA, 2);
        sB += __shfl_xor_sync(0xffffffffu, sB, 1);
        sB += __shfl_xor_sync(0xffffffffu, sB, 2);
        float iA = __frcp_rn(sA), iB = __frcp_rn(sB);
        #pragma unroll
        for (int nt = 0; nt < 8; ++nt) {
            s2[nt][0] *= iA; s2[nt][1] *= iA;
            s2[nt][2] *= iB; s2[nt][3] *= iB;
        }
    }

    // ================= Phase 3: O = P @ V (A fragments built in-register) ====
    const uint32_t* VH32 = (const uint32_t*)(sm + A2OFF(4, bb2));
    const uint32_t* VL32 = (const uint32_t*)(sm + A2OFF(5, bb2));
    float o[8][4];
    #pragma unroll
    for (int n = 0; n < 8; n++)
        #pragma unroll
        for (int e = 0; e < 4; e++) o[n][e] = 0.f;

    #pragma unroll
    for (int kt = 0; kt < 4; ++kt) {
        uint32_t ah0, ah1, ah2, ah3, al0, al1, al2, al3;
        sp2(s2[2 * kt][0],     s2[2 * kt][1],     ah0, al0);
        sp2(s2[2 * kt][2],     s2[2 * kt][3],     ah1, al1);
        sp2(s2[2 * kt + 1][0], s2[2 * kt + 1][1], ah2, al2);
        sp2(s2[2 * kt + 1][2], s2[2 * kt + 1][3], ah3, al3);
        #pragma unroll
        for (int nt = 0; nt < 8; ++nt) {
            int n = nt * 8 + lr;
            int bi = n * 36 + kt * 8 + qk;
            uint32_t bh0 = VH32[bi], bh1 = VH32[bi + 4];
            uint32_t bl0 = VL32[bi], bl1 = VL32[bi + 4];
            mma16816(o[nt], ah0, ah1, ah2, ah3, bh0, bh1);
            mma16816(o[nt], al0, al1, al2, al3, bh0, bh1);
            mma16816(o[nt], ah0, ah1, ah2, ah3, bl0, bl1);
        }
    }

    // ---- store O ----
    {
        float* ob = out + ((size_t)(b0 + bb2) * TT) * HH;
        #pragma unroll
        for (int nt = 0; nt < 8; ++nt) {
            int c0 = nt * 8 + qk * 2;
            *(float2*)&ob[rowA * HH + c0] = make_float2(o[nt][0], o[nt][1]);
            *(float2*)&ob[rowB * HH + c0] = make_float2(o[nt][2], o[nt][3]);
        }
    }
}

extern "C" void kernel_launch(void* const* d_in, const int* in_sizes, int n_in,
                              void* d_out, int out_size) {
    const float* x  = (const float*)d_in[0];
    const float* Wq = (const float*)d_in[1];
    const float* Wk = (const float*)d_in[2];
    const float* Wv = (const float*)d_in[3];
    float* out = (float*)d_out;

    int B = in_sizes[0] / (TT * CC);

    prep_w_kernel<<<24, 256>>>(Wq, Wk, Wv);

    cudaFuncSetAttribute(DiqqetBashi_hmma2_kernel,
                         cudaFuncAttributeMaxDynamicSharedMemorySize, SMEM_BYTES);
    DiqqetBashi_hmma2_kernel<<<B / 2, 256, SMEM_BYTES>>>(x, out);
}

// round 6
// speedup vs baseline: 4.0736x; 1.3606x over previous
#include <cuda_runtime.h>
#include <cuda_fp16.h>
#include <stdint.h>

#define TT 64
#define CC 128
#define HH 64
#define SCALE_Q 0.08838834764831844f   // 128^-0.5

// W single-fp16 fragment-ordered: [nt(24)][kt(8)][lane(32)] -> {b0,b1}
__device__ uint2 WFRAG[6144];

// ---------------- smem arena (byte offsets) ----------------
// Phase 1: XH [128 x 136 halves] @0 (34816B), XL @34816  -- aliased by:
// Phase 2/3: arr 0=QH 1=QL 2=K 3=VT ; each [64 x 72] fp16 per batch
#define SMEM_BYTES 73728
#define LDX 136
#define LD2 72
#define A2OFF(arr, b) ((arr) * 18432 + (b) * 9216)

// ---------------- helpers ----------------
__device__ __forceinline__ void sp2h(float v0, float v1, uint32_t& H, uint32_t& L) {
    __half2 h = __floats2half2_rn(v0, v1);
    float r0 = v0 - __half2float(__low2half(h));
    float r1 = v1 - __half2float(__high2half(h));
    __half2 l = __floats2half2_rn(r0, r1);
    H = *(uint32_t*)&h;
    L = *(uint32_t*)&l;
}
__device__ __forceinline__ uint32_t h2pack(float v0, float v1) {
    __half2 h = __floats2half2_rn(v0, v1);
    return *(uint32_t*)&h;
}
__device__ __forceinline__ void mma16816(float* c,
                                         uint32_t a0, uint32_t a1, uint32_t a2, uint32_t a3,
                                         uint32_t b0, uint32_t b1) {
    asm volatile(
        "mma.sync.aligned.m16n8k16.row.col.f32.f16.f16.f32 "
        "{%0,%1,%2,%3}, {%4,%5,%6,%7}, {%8,%9}, {%0,%1,%2,%3};"
        : "+f"(c[0]), "+f"(c[1]), "+f"(c[2]), "+f"(c[3])
        : "r"(a0), "r"(a1), "r"(a2), "r"(a3), "r"(b0), "r"(b1));
}

// ---------------- prep kernel: W -> fragment-ordered fp16 global ----------------
__global__ void prep_w_kernel(const float* __restrict__ Wq,
                              const float* __restrict__ Wk,
                              const float* __restrict__ Wv) {
    int i = blockIdx.x * 256 + threadIdx.x;
    if (i >= 6144) return;
    int lane = i & 31;
    int kt   = (i >> 5) & 7;
    int nt   = i >> 8;
    int qk = lane & 3, lr = lane >> 2;
    int n = nt * 8 + lr;
    int g = n >> 6, h = n & 63;
    const float* Wg = (g == 0) ? Wq : (g == 1) ? Wk : Wv;
    float s = (g == 0) ? SCALE_Q : 1.0f;
    int k0 = kt * 16 + qk * 2;
    float w0 = Wg[(k0    ) * HH + h] * s;
    float w1 = Wg[(k0 + 1) * HH + h] * s;
    float w2 = Wg[(k0 + 8) * HH + h] * s;
    float w3 = Wg[(k0 + 9) * HH + h] * s;
    WFRAG[i] = make_uint2(h2pack(w0, w1), h2pack(w2, w3));
}

// ---------------- main kernel ----------------
__global__ void __launch_bounds__(256, 2)
DiqqetBashi_hmma3_kernel(const float* __restrict__ x,
                         float* __restrict__ out) {
    extern __shared__ char sm[];
    const int tid  = threadIdx.x;
    const int wid  = tid >> 5;
    const int lane = tid & 31;
    const int qk   = lane & 3;
    const int lr   = lane >> 2;
    const int b0   = blockIdx.x * 2;

    uint16_t* XH = (uint16_t*)sm;
    uint16_t* XL = (uint16_t*)(sm + 34816);

    // ---- stage X (2 batches = 128 rows x 128 cols f32) -> fp16 split ----
    {
        const float4* x4 = (const float4*)(x + (size_t)b0 * TT * CC);
        #pragma unroll
        for (int it = 0; it < 16; ++it) {
            int idx = tid + it * 256;
            int r = idx >> 5, c0 = (idx & 31) << 2;
            float4 v = x4[idx];
            uint32_t h01, l01, h23, l23;
            sp2h(v.x, v.y, h01, l01);
            sp2h(v.z, v.w, h23, l23);
            *(unsigned long long*)&XH[r * LDX + c0] =
                (unsigned long long)h01 | ((unsigned long long)h23 << 32);
            *(unsigned long long*)&XL[r * LDX + c0] =
                (unsigned long long)l01 | ((unsigned long long)l23 << 32);
        }
    }
    __syncthreads();

    // ================= Phase 1: QKV[128,192] = X[128,128] @ W ================
    // warp owns cols [wid*24, wid*24+24) (3 n-tiles), all 128 rows (8 m-tiles)
    float acc[8][3][4];
    #pragma unroll
    for (int m = 0; m < 8; m++)
        #pragma unroll
        for (int j = 0; j < 3; j++)
            #pragma unroll
            for (int e = 0; e < 4; e++) acc[m][j][e] = 0.f;

    const uint32_t* XH32 = (const uint32_t*)XH;
    const uint32_t* XL32 = (const uint32_t*)XL;

    #pragma unroll
    for (int kt = 0; kt < 8; ++kt) {
        uint2 B0 = WFRAG[((wid * 3 + 0) * 8 + kt) * 32 + lane];
        uint2 B1 = WFRAG[((wid * 3 + 1) * 8 + kt) * 32 + lane];
        uint2 B2 = WFRAG[((wid * 3 + 2) * 8 + kt) * 32 + lane];
        #pragma unroll
        for (int m = 0; m < 8; ++m) {
            int ab = (m * 16 + lr) * 68 + kt * 8 + qk;
            uint32_t ah0 = XH32[ab],     ah1 = XH32[ab + 8 * 68];
            uint32_t ah2 = XH32[ab + 4], ah3 = XH32[ab + 8 * 68 + 4];
            uint32_t al0 = XL32[ab],     al1 = XL32[ab + 8 * 68];
            uint32_t al2 = XL32[ab + 4], al3 = XL32[ab + 8 * 68 + 4];
            mma16816(acc[m][0], ah0, ah1, ah2, ah3, B0.x, B0.y);
            mma16816(acc[m][0], al0, al1, al2, al3, B0.x, B0.y);
            mma16816(acc[m][1], ah0, ah1, ah2, ah3, B1.x, B1.y);
            mma16816(acc[m][1], al0, al1, al2, al3, B1.x, B1.y);
            mma16816(acc[m][2], ah0, ah1, ah2, ah3, B2.x, B2.y);
            mma16816(acc[m][2], al0, al1, al2, al3, B2.x, B2.y);
        }
    }
    __syncthreads();   // X reads done before arena overwrite

    // ---- writeback: Q split [t][h]; K single [t][h]; V single transposed [h][t]
    #pragma unroll
    for (int m = 0; m < 8; ++m) {
        int rA = m * 16 + lr;
        int rB = rA + 8;
        int b_ = rA >> 6;
        int tA = rA & 63, tB = rB & 63;
        #pragma unroll
        for (int j = 0; j < 3; ++j) {
            int colbase = wid * 24 + j * 8;
            int rg = colbase >> 6;          // 0=Q 1=K 2=V
            int off = colbase & 63;
            float* a = acc[m][j];
            if (rg == 0) {
                uint32_t* DH = (uint32_t*)(sm + A2OFF(0, b_));
                uint32_t* DL = (uint32_t*)(sm + A2OFF(1, b_));
                int ci = (off >> 1) + qk;
                uint32_t H, L;
                sp2h(a[0], a[1], H, L); DH[tA * 36 + ci] = H; DL[tA * 36 + ci] = L;
                sp2h(a[2], a[3], H, L); DH[tB * 36 + ci] = H; DL[tB * 36 + ci] = L;
            } else if (rg == 1) {
                uint32_t* DK = (uint32_t*)(sm + A2OFF(2, b_));
                int ci = (off >> 1) + qk;
                DK[tA * 36 + ci] = h2pack(a[0], a[1]);
                DK[tB * 36 + ci] = h2pack(a[2], a[3]);
            } else {
                uint16_t* VH = (uint16_t*)(sm + A2OFF(3, b_));
                int h0 = off + qk * 2;
                VH[h0 * LD2 + tA]       = __half_as_ushort(__float2half_rn(a[0]));
                VH[(h0 + 1) * LD2 + tA] = __half_as_ushort(__float2half_rn(a[1]));
                VH[h0 * LD2 + tB]       = __half_as_ushort(__float2half_rn(a[2]));
                VH[(h0 + 1) * LD2 + tB] = __half_as_ushort(__float2half_rn(a[3]));
            }
        }
    }
    __syncthreads();

    // ================= Phase 2: S = Q @ K^T (per batch, in registers) ========
    const int bb2 = wid >> 2;            // batch
    const int mrow = (wid & 3) * 16;     // 16-row block within batch
    const uint32_t* QH32 = (const uint32_t*)(sm + A2OFF(0, bb2));
    const uint32_t* QL32 = (const uint32_t*)(sm + A2OFF(1, bb2));
    const uint32_t* KK32 = (const uint32_t*)(sm + A2OFF(2, bb2));

    float s2[8][4];
    #pragma unroll
    for (int n = 0; n < 8; n++)
        #pragma unroll
        for (int e = 0; e < 4; e++) s2[n][e] = 0.f;

    #pragma unroll
    for (int kt = 0; kt < 4; ++kt) {
        int rA = mrow + lr;
        int ab = rA * 36 + kt * 8 + qk;
        uint32_t ah0 = QH32[ab],     ah1 = QH32[ab + 8 * 36];
        uint32_t ah2 = QH32[ab + 4], ah3 = QH32[ab + 8 * 36 + 4];
        uint32_t al0 = QL32[ab],     al1 = QL32[ab + 8 * 36];
        uint32_t al2 = QL32[ab + 4], al3 = QL32[ab + 8 * 36 + 4];
        #pragma unroll
        for (int nt = 0; nt < 8; ++nt) {
            int n = nt * 8 + lr;
            int bi = n * 36 + kt * 8 + qk;
            uint32_t bh0 = KK32[bi], bh1 = KK32[bi + 4];
            mma16816(s2[nt], ah0, ah1, ah2, ah3, bh0, bh1);
            mma16816(s2[nt], al0, al1, al2, al3, bh0, bh1);
        }
    }

    // ---- causal softmax in registers ----
    const int rowA = mrow + lr, rowB = rowA + 8;
    {
        float mA = -1e30f, mB = -1e30f;
        #pragma unroll
        for (int nt = 0; nt < 8; ++nt) {
            int c0 = nt * 8 + qk * 2;
            s2[nt][0] = (c0     <= rowA) ? s2[nt][0] : -1e30f;
            s2[nt][1] = (c0 + 1 <= rowA) ? s2[nt][1] : -1e30f;
            s2[nt][2] = (c0     <= rowB) ? s2[nt][2] : -1e30f;
            s2[nt][3] = (c0 + 1 <= rowB) ? s2[nt][3] : -1e30f;
            mA = fmaxf(mA, fmaxf(s2[nt][0], s2[nt][1]));
            mB = fmaxf(mB, fmaxf(s2[nt][2], s2[nt][3]));
        }
        mA = fmaxf(mA, __shfl_xor_sync(0xffffffffu, mA, 1));
        mA = fmaxf(mA, __shfl_xor_sync(0xffffffffu, mA, 2));
        mB = fmaxf(mB, __shfl_xor_sync(0xffffffffu, mB, 1));
        mB = fmaxf(mB, __shfl_xor_sync(0xffffffffu, mB, 2));
        float sA = 0.f, sB = 0.f;
        #pragma unroll
        for (int nt = 0; nt < 8; ++nt) {
            int c0 = nt * 8 + qk * 2;
            float e0 = (c0     <= rowA) ? __expf(s2[nt][0] - mA) : 0.f;
            float e1 = (c0 + 1 <= rowA) ? __expf(s2[nt][1] - mA) : 0.f;
            float e2 = (c0     <= rowB) ? __expf(s2[nt][2] - mB) : 0.f;
            float e3 = (c0 + 1 <= rowB) ? __expf(s2[nt][3] - mB) : 0.f;
            s2[nt][0] = e0; s2[nt][1] = e1; s2[nt][2] = e2; s2[nt][3] = e3;
            sA += e0 + e1;  sB += e2 + e3;
        }
        sA += __shfl_xor_sync(0xffffffffu, sA, 1);
        sA += __shfl_xor_sync(0xffffffffu, sA, 2);
        sB += __shfl_xor_sync(0xffffffffu, sB, 1);
        sB += __shfl_xor_sync(0xffffffffu, sB, 2);
        float iA = __frcp_rn(sA), iB = __frcp_rn(sB);
        #pragma unroll
        for (int nt = 0; nt < 8; ++nt) {
            s2[nt][0] *= iA; s2[nt][1] *= iA;
            s2[nt][2] *= iB; s2[nt][3] *= iB;
        }
    }

    // ================= Phase 3: O = P @ V (A fragments built in-register) ====
    const uint32_t* VV32 = (const uint32_t*)(sm + A2OFF(3, bb2));
    float o[8][4];
    #pragma unroll
    for (int n = 0; n < 8; n++)
        #pragma unroll
        for (int e = 0; e < 4; e++) o[n][e] = 0.f;

    #pragma unroll
    for (int kt = 0; kt < 4; ++kt) {
        uint32_t ah0, ah1, ah2, ah3, al0, al1, al2, al3;
        sp2h(s2[2 * kt][0],     s2[2 * kt][1],     ah0, al0);
        sp2h(s2[2 * kt][2],     s2[2 * kt][3],     ah1, al1);
        sp2h(s2[2 * kt + 1][0], s2[2 * kt + 1][1], ah2, al2);
        sp2h(s2[2 * kt + 1][2], s2[2 * kt + 1][3], ah3, al3);
        #pragma unroll
        for (int nt = 0; nt < 8; ++nt) {
            int n = nt * 8 + lr;
            int bi = n * 36 + kt * 8 + qk;
            uint32_t bh0 = VV32[bi], bh1 = VV32[bi + 4];
            mma16816(o[nt], ah0, ah1, ah2, ah3, bh0, bh1);
            mma16816(o[nt], al0, al1, al2, al3, bh0, bh1);
        }
    }

    // ---- store O ----
    {
        float* ob = out + ((size_t)(b0 + bb2) * TT) * HH;
        #pragma unroll
        for (int nt = 0; nt < 8; ++nt) {
            int c0 = nt * 8 + qk * 2;
            *(float2*)&ob[rowA * HH + c0] = make_float2(o[nt][0], o[nt][1]);
            *(float2*)&ob[rowB * HH + c0] = make_float2(o[nt][2], o[nt][3]);
        }
    }
}

extern "C" void kernel_launch(void* const* d_in, const int* in_sizes, int n_in,
                              void* d_out, int out_size) {
    const float* x  = (const float*)d_in[0];
    const float* Wq = (const float*)d_in[1];
    const float* Wk = (const float*)d_in[2];
    const float* Wv = (const float*)d_in[3];
    float* out = (float*)d_out;

    int B = in_sizes[0] / (TT * CC);

    prep_w_kernel<<<24, 256>>>(Wq, Wk, Wv);

    cudaFuncSetAttribute(DiqqetBashi_hmma3_kernel,
                         cudaFuncAttributeMaxDynamicSharedMemorySize, SMEM_BYTES);
    DiqqetBashi_hmma3_kernel<<<B / 2, 256, SMEM_BYTES>>>(x, out);
}

// round 7
// speedup vs baseline: 4.2086x; 1.0331x over previous
#include <cuda_runtime.h>
#include <cuda_fp16.h>
#include <stdint.h>

#define TT 64
#define CC 128
#define HH 64
#define SCALE_Q 0.08838834764831844f   // 128^-0.5

// W single-fp16 fragment-ordered: [nt(24)][kt(8)][lane(32)] -> {b0,b1}
__device__ uint2 WFRAG[6144];

// ---------------- smem arena (byte offsets) ----------------
// Phase 1: XH [128 x 136 halves] @0 (34816B), XL @34816  -- aliased by:
// Phase 2/3: arr 0=QH 1=QL 2=K 3=VT ; each [64 x 72] fp16 per batch
#define SMEM_BYTES 73728
#define LDX 136
#define LD2 72
#define A2OFF(arr, b) ((arr) * 18432 + (b) * 9216)

// ---------------- helpers ----------------
__device__ __forceinline__ void sp2h(float v0, float v1, uint32_t& H, uint32_t& L) {
    __half2 h = __floats2half2_rn(v0, v1);
    float r0 = v0 - __half2float(__low2half(h));
    float r1 = v1 - __half2float(__high2half(h));
    __half2 l = __floats2half2_rn(r0, r1);
    H = *(uint32_t*)&h;
    L = *(uint32_t*)&l;
}
__device__ __forceinline__ uint32_t h2pack(float v0, float v1) {
    __half2 h = __floats2half2_rn(v0, v1);
    return *(uint32_t*)&h;
}
// NOTE: non-volatile — pure register op, let ptxas schedule freely
__device__ __forceinline__ void mma16816(float* c,
                                         uint32_t a0, uint32_t a1, uint32_t a2, uint32_t a3,
                                         uint32_t b0, uint32_t b1) {
    asm("mma.sync.aligned.m16n8k16.row.col.f32.f16.f16.f32 "
        "{%0,%1,%2,%3}, {%4,%5,%6,%7}, {%8,%9}, {%0,%1,%2,%3};"
        : "+f"(c[0]), "+f"(c[1]), "+f"(c[2]), "+f"(c[3])
        : "r"(a0), "r"(a1), "r"(a2), "r"(a3), "r"(b0), "r"(b1));
}
// ldmatrix x4: one instruction loads the full m16k16 A fragment
__device__ __forceinline__ void ldsm4(uint32_t addr, uint32_t& r0, uint32_t& r1,
                                      uint32_t& r2, uint32_t& r3) {
    asm("ldmatrix.sync.aligned.m8n8.x4.shared.b16 {%0,%1,%2,%3}, [%4];"
        : "=r"(r0), "=r"(r1), "=r"(r2), "=r"(r3) : "r"(addr) : "memory");
}

// ---------------- prep kernel: W -> fragment-ordered fp16 global ----------------
__global__ void prep_w_kernel(const float* __restrict__ Wq,
                              const float* __restrict__ Wk,
                              const float* __restrict__ Wv) {
    int i = blockIdx.x * 256 + threadIdx.x;
    if (i >= 6144) return;
    int lane = i & 31;
    int kt   = (i >> 5) & 7;
    int nt   = i >> 8;
    int qk = lane & 3, lr = lane >> 2;
    int n = nt * 8 + lr;
    int g = n >> 6, h = n & 63;
    const float* Wg = (g == 0) ? Wq : (g == 1) ? Wk : Wv;
    float s = (g == 0) ? SCALE_Q : 1.0f;
    int k0 = kt * 16 + qk * 2;
    float w0 = Wg[(k0    ) * HH + h] * s;
    float w1 = Wg[(k0 + 1) * HH + h] * s;
    float w2 = Wg[(k0 + 8) * HH + h] * s;
    float w3 = Wg[(k0 + 9) * HH + h] * s;
    WFRAG[i] = make_uint2(h2pack(w0, w1), h2pack(w2, w3));
}

// ---------------- main kernel ----------------
__global__ void __launch_bounds__(256, 2)
DiqqetBashi_hmma4_kernel(const float* __restrict__ x,
                         float* __restrict__ out) {
    extern __shared__ char sm[];
    const int tid  = threadIdx.x;
    const int wid  = tid >> 5;
    const int lane = tid & 31;
    const int qk   = lane & 3;
    const int lr   = lane >> 2;
    const int b0   = blockIdx.x * 2;

    const uint32_t smb = (uint32_t)__cvta_generic_to_shared(sm);
    // per-lane ldmatrix row/colhalf offset for a given row stride (bytes)
    const int lmRow  = (lane & 7) + ((lane >> 3) & 1) * 8;
    const int lmCol  = (lane >> 4) * 16;

    uint16_t* XH = (uint16_t*)sm;
    uint16_t* XL = (uint16_t*)(sm + 34816);

    // ---- stage X (2 batches = 128 rows x 128 cols f32) -> fp16 split ----
    {
        const float4* x4 = (const float4*)(x + (size_t)b0 * TT * CC);
        #pragma unroll
        for (int it = 0; it < 16; ++it) {
            int idx = tid + it * 256;
            int r = idx >> 5, c0 = (idx & 31) << 2;
            float4 v = x4[idx];
            uint32_t h01, l01, h23, l23;
            sp2h(v.x, v.y, h01, l01);
            sp2h(v.z, v.w, h23, l23);
            *(unsigned long long*)&XH[r * LDX + c0] =
                (unsigned long long)h01 | ((unsigned long long)h23 << 32);
            *(unsigned long long*)&XL[r * LDX + c0] =
                (unsigned long long)l01 | ((unsigned long long)l23 << 32);
        }
    }
    __syncthreads();

    // ================= Phase 1: QKV[128,192] = X[128,128] @ W ================
    // warp owns cols [wid*24, wid*24+24) (3 n-tiles), all 128 rows (8 m-tiles)
    float acc[8][3][4];
    #pragma unroll
    for (int m = 0; m < 8; m++)
        #pragma unroll
        for (int j = 0; j < 3; j++)
            #pragma unroll
            for (int e = 0; e < 4; e++) acc[m][j][e] = 0.f;

    // X fragment ldmatrix lane base (stride 272 B per row)
    const uint32_t xlmBase = smb + (uint32_t)(lmRow * 272 + lmCol);

    #pragma unroll
    for (int kt = 0; kt < 8; ++kt) {
        uint2 B0 = WFRAG[((wid * 3 + 0) * 8 + kt) * 32 + lane];
        uint2 B1 = WFRAG[((wid * 3 + 1) * 8 + kt) * 32 + lane];
        uint2 B2 = WFRAG[((wid * 3 + 2) * 8 + kt) * 32 + lane];
        #pragma unroll
        for (int m = 0; m < 8; ++m) {
            uint32_t aH = xlmBase + (uint32_t)(m * 16 * 272 + kt * 32);
            uint32_t ah0, ah1, ah2, ah3, al0, al1, al2, al3;
            ldsm4(aH,         ah0, ah1, ah2, ah3);
            ldsm4(aH + 34816, al0, al1, al2, al3);
            // hi chains first (independent accs), then lo chains
            mma16816(acc[m][0], ah0, ah1, ah2, ah3, B0.x, B0.y);
            mma16816(acc[m][1], ah0, ah1, ah2, ah3, B1.x, B1.y);
            mma16816(acc[m][2], ah0, ah1, ah2, ah3, B2.x, B2.y);
            mma16816(acc[m][0], al0, al1, al2, al3, B0.x, B0.y);
            mma16816(acc[m][1], al0, al1, al2, al3, B1.x, B1.y);
            mma16816(acc[m][2], al0, al1, al2, al3, B2.x, B2.y);
        }
    }
    __syncthreads();   // X reads done before arena overwrite

    // ---- writeback: Q split [t][h]; K single [t][h]; V single transposed [h][t]
    #pragma unroll
    for (int m = 0; m < 8; ++m) {
        int rA = m * 16 + lr;
        int rB = rA + 8;
        int b_ = rA >> 6;
        int tA = rA & 63, tB = rB & 63;
        #pragma unroll
        for (int j = 0; j < 3; ++j) {
            int colbase = wid * 24 + j * 8;
            int rg = colbase >> 6;          // 0=Q 1=K 2=V
            int off = colbase & 63;
            float* a = acc[m][j];
            if (rg == 0) {
                uint32_t* DH = (uint32_t*)(sm + A2OFF(0, b_));
                uint32_t* DL = (uint32_t*)(sm + A2OFF(1, b_));
                int ci = (off >> 1) + qk;
                uint32_t H, L;
                sp2h(a[0], a[1], H, L); DH[tA * 36 + ci] = H; DL[tA * 36 + ci] = L;
                sp2h(a[2], a[3], H, L); DH[tB * 36 + ci] = H; DL[tB * 36 + ci] = L;
            } else if (rg == 1) {
                uint32_t* DK = (uint32_t*)(sm + A2OFF(2, b_));
                int ci = (off >> 1) + qk;
                DK[tA * 36 + ci] = h2pack(a[0], a[1]);
                DK[tB * 36 + ci] = h2pack(a[2], a[3]);
            } else {
                uint16_t* VH = (uint16_t*)(sm + A2OFF(3, b_));
                int h0 = off + qk * 2;
                VH[h0 * LD2 + tA]       = __half_as_ushort(__float2half_rn(a[0]));
                VH[(h0 + 1) * LD2 + tA] = __half_as_ushort(__float2half_rn(a[1]));
                VH[h0 * LD2 + tB]       = __half_as_ushort(__float2half_rn(a[2]));
                VH[(h0 + 1) * LD2 + tB] = __half_as_ushort(__float2half_rn(a[3]));
            }
        }
    }
    __syncthreads();

    // ================= Phase 2: S = Q @ K^T (per batch, in registers) ========
    const int bb2 = wid >> 2;            // batch
    const int mrow = (wid & 3) * 16;     // 16-row block within batch
    const uint32_t* KK32 = (const uint32_t*)(sm + A2OFF(2, bb2));

    float s2[8][4];
    #pragma unroll
    for (int n = 0; n < 8; n++)
        #pragma unroll
        for (int e = 0; e < 4; e++) s2[n][e] = 0.f;

    // Q fragment ldmatrix base (stride 144 B per row)
    const uint32_t qlmBase = smb + (uint32_t)(A2OFF(0, bb2) + mrow * 144 + lmRow * 144 + lmCol);

    #pragma unroll
    for (int kt = 0; kt < 4; ++kt) {
        uint32_t aQ = qlmBase + (uint32_t)(kt * 32);
        uint32_t ah0, ah1, ah2, ah3, al0, al1, al2, al3;
        ldsm4(aQ,         ah0, ah1, ah2, ah3);
        ldsm4(aQ + 18432, al0, al1, al2, al3);   // QL = QH + A2OFF step
        #pragma unroll
        for (int nt = 0; nt < 8; ++nt) {
            int n = nt * 8 + lr;
            int bi = n * 36 + kt * 8 + qk;
            uint32_t bh0 = KK32[bi], bh1 = KK32[bi + 4];
            mma16816(s2[nt], ah0, ah1, ah2, ah3, bh0, bh1);
            mma16816(s2[nt], al0, al1, al2, al3, bh0, bh1);
        }
    }

    // ---- causal softmax in registers ----
    const int rowA = mrow + lr, rowB = rowA + 8;
    {
        float mA = -1e30f, mB = -1e30f;
        #pragma unroll
        for (int nt = 0; nt < 8; ++nt) {
            int c0 = nt * 8 + qk * 2;
            s2[nt][0] = (c0     <= rowA) ? s2[nt][0] : -1e30f;
            s2[nt][1] = (c0 + 1 <= rowA) ? s2[nt][1] : -1e30f;
            s2[nt][2] = (c0     <= rowB) ? s2[nt][2] : -1e30f;
            s2[nt][3] = (c0 + 1 <= rowB) ? s2[nt][3] : -1e30f;
            mA = fmaxf(mA, fmaxf(s2[nt][0], s2[nt][1]));
            mB = fmaxf(mB, fmaxf(s2[nt][2], s2[nt][3]));
        }
        mA = fmaxf(mA, __shfl_xor_sync(0xffffffffu, mA, 1));
        mA = fmaxf(mA, __shfl_xor_sync(0xffffffffu, mA, 2));
        mB = fmaxf(mB, __shfl_xor_sync(0xffffffffu, mB, 1));
        mB = fmaxf(mB, __shfl_xor_sync(0xffffffffu, mB, 2));
        float sA = 0.f, sB = 0.f;
        #pragma unroll
        for (int nt = 0; nt < 8; ++nt) {
            int c0 = nt * 8 + qk * 2;
            float e0 = (c0     <= rowA) ? __expf(s2[nt][0] - mA) : 0.f;
            float e1 = (c0 + 1 <= rowA) ? __expf(s2[nt][1] - mA) : 0.f;
            float e2 = (c0     <= rowB) ? __expf(s2[nt][2] - mB) : 0.f;
            float e3 = (c0 + 1 <= rowB) ? __expf(s2[nt][3] - mB) : 0.f;
            s2[nt][0] = e0; s2[nt][1] = e1; s2[nt][2] = e2; s2[nt][3] = e3;
            sA += e0 + e1;  sB += e2 + e3;
        }
        sA += __shfl_xor_sync(0xffffffffu, sA, 1);
        sA += __shfl_xor_sync(0xffffffffu, sA, 2);
        sB += __shfl_xor_sync(0xffffffffu, sB, 1);
        sB += __shfl_xor_sync(0xffffffffu, sB, 2);
        float iA = __frcp_rn(sA), iB = __frcp_rn(sB);
        #pragma unroll
        for (int nt = 0; nt < 8; ++nt) {
            s2[nt][0] *= iA; s2[nt][1] *= iA;
            s2[nt][2] *= iB; s2[nt][3] *= iB;
        }
    }

    // ================= Phase 3: O = P @ V (A fragments built in-register) ====
    const uint32_t* VV32 = (const uint32_t*)(sm + A2OFF(3, bb2));
    float o[8][4];
    #pragma unroll
    for (int n = 0; n < 8; n++)
        #pragma unroll
        for (int e = 0; e < 4; e++) o[n][e] = 0.f;

    #pragma unroll
    for (int kt = 0; kt < 4; ++kt) {
        uint32_t ah0, ah1, ah2, ah3, al0, al1, al2, al3;
        sp2h(s2[2 * kt][0],     s2[2 * kt][1],     ah0, al0);
        sp2h(s2[2 * kt][2],     s2[2 * kt][3],     ah1, al1);
        sp2h(s2[2 * kt + 1][0], s2[2 * kt + 1][1], ah2, al2);
        sp2h(s2[2 * kt + 1][2], s2[2 * kt + 1][3], ah3, al3);
        #pragma unroll
        for (int nt = 0; nt < 8; ++nt) {
            int n = nt * 8 + lr;
            int bi = n * 36 + kt * 8 + qk;
            uint32_t bh0 = VV32[bi], bh1 = VV32[bi + 4];
            mma16816(o[nt], ah0, ah1, ah2, ah3, bh0, bh1);
            mma16816(o[nt], al0, al1, al2, al3, bh0, bh1);
        }
    }

    // ---- store O ----
    {
        float* ob = out + ((size_t)(b0 + bb2) * TT) * HH;
        #pragma unroll
        for (int nt = 0; nt < 8; ++nt) {
            int c0 = nt * 8 + qk * 2;
            *(float2*)&ob[rowA * HH + c0] = make_float2(o[nt][0], o[nt][1]);
            *(float2*)&ob[rowB * HH + c0] = make_float2(o[nt][2], o[nt][3]);
        }
    }
}

extern "C" void kernel_launch(void* const* d_in, const int* in_sizes, int n_in,
                              void* d_out, int out_size) {
    const float* x  = (const float*)d_in[0];
    const float* Wq = (const float*)d_in[1];
    const float* Wk = (const float*)d_in[2];
    const float* Wv = (const float*)d_in[3];
    float* out = (float*)d_out;

    int B = in_sizes[0] / (TT * CC);

    prep_w_kernel<<<24, 256>>>(Wq, Wk, Wv);

    cudaFuncSetAttribute(DiqqetBashi_hmma4_kernel,
                         cudaFuncAttributeMaxDynamicSharedMemorySize, SMEM_BYTES);
    DiqqetBashi_hmma4_kernel<<<B / 2, 256, SMEM_BYTES>>>(x, out);
}

// round 8
// speedup vs baseline: 5.4285x; 1.2899x over previous
#include <cuda_runtime.h>
#include <cuda_fp16.h>
#include <stdint.h>

#define TT 64
#define CC 128
#define HH 64
#define SCALE_Q 0.08838834764831844f   // 128^-0.5

// W single-fp16 fragment-ordered: [nt(24)][kt(8)][lane(32)] -> {b0,b1}
__device__ uint2 WFRAG[6144];

// ---------------- smem arena (byte offsets) ----------------
// Phase 1: XH [128 x 136 halves] @0 (34816B)  -- aliased by:
// Phase 2/3: arr 0=QH 1=QL 2=K 3=VT ; each [64 x 72] fp16 per batch
#define SMEM_BYTES 73728
#define LDX 136
#define LD2 72
#define A2OFF(arr, b) ((arr) * 18432 + (b) * 9216)

// ---------------- helpers ----------------
__device__ __forceinline__ void sp2h(float v0, float v1, uint32_t& H, uint32_t& L) {
    __half2 h = __floats2half2_rn(v0, v1);
    float r0 = v0 - __half2float(__low2half(h));
    float r1 = v1 - __half2float(__high2half(h));
    __half2 l = __floats2half2_rn(r0, r1);
    H = *(uint32_t*)&h;
    L = *(uint32_t*)&l;
}
__device__ __forceinline__ uint32_t h2pack(float v0, float v1) {
    __half2 h = __floats2half2_rn(v0, v1);
    return *(uint32_t*)&h;
}
// non-volatile — pure register op, let ptxas schedule freely
__device__ __forceinline__ void mma16816(float* c,
                                         uint32_t a0, uint32_t a1, uint32_t a2, uint32_t a3,
                                         uint32_t b0, uint32_t b1) {
    asm("mma.sync.aligned.m16n8k16.row.col.f32.f16.f16.f32 "
        "{%0,%1,%2,%3}, {%4,%5,%6,%7}, {%8,%9}, {%0,%1,%2,%3};"
        : "+f"(c[0]), "+f"(c[1]), "+f"(c[2]), "+f"(c[3])
        : "r"(a0), "r"(a1), "r"(a2), "r"(a3), "r"(b0), "r"(b1));
}
__device__ __forceinline__ void ldsm4(uint32_t addr, uint32_t& r0, uint32_t& r1,
                                      uint32_t& r2, uint32_t& r3) {
    asm("ldmatrix.sync.aligned.m8n8.x4.shared.b16 {%0,%1,%2,%3}, [%4];"
        : "=r"(r0), "=r"(r1), "=r"(r2), "=r"(r3) : "r"(addr) : "memory");
}

// ---------------- prep kernel: W -> fragment-ordered fp16 global ----------------
__global__ void prep_w_kernel(const float* __restrict__ Wq,
                              const float* __restrict__ Wk,
                              const float* __restrict__ Wv) {
    int i = blockIdx.x * 256 + threadIdx.x;
    if (i >= 6144) return;
    int lane = i & 31;
    int kt   = (i >> 5) & 7;
    int nt   = i >> 8;
    int qk = lane & 3, lr = lane >> 2;
    int n = nt * 8 + lr;
    int g = n >> 6, h = n & 63;
    const float* Wg = (g == 0) ? Wq : (g == 1) ? Wk : Wv;
    float s = (g == 0) ? SCALE_Q : 1.0f;
    int k0 = kt * 16 + qk * 2;
    float w0 = Wg[(k0    ) * HH + h] * s;
    float w1 = Wg[(k0 + 1) * HH + h] * s;
    float w2 = Wg[(k0 + 8) * HH + h] * s;
    float w3 = Wg[(k0 + 9) * HH + h] * s;
    WFRAG[i] = make_uint2(h2pack(w0, w1), h2pack(w2, w3));
}

// ---------------- main kernel ----------------
__global__ void __launch_bounds__(256, 2)
DiqqetBashi_hmma5_kernel(const float* __restrict__ x,
                         float* __restrict__ out) {
    extern __shared__ char sm[];
    const int tid  = threadIdx.x;
    const int wid  = tid >> 5;
    const int lane = tid & 31;
    const int qk   = lane & 3;
    const int lr   = lane >> 2;
    const int b0   = blockIdx.x * 2;

    const uint32_t smb = (uint32_t)__cvta_generic_to_shared(sm);
    const int lmRow  = (lane & 7) + ((lane >> 3) & 1) * 8;
    const int lmCol  = (lane >> 4) * 16;

    uint16_t* XH = (uint16_t*)sm;

    // ---- stage X (2 batches = 128 rows x 128 cols f32) -> single fp16 ----
    {
        const float4* x4 = (const float4*)(x + (size_t)b0 * TT * CC);
        #pragma unroll
        for (int it = 0; it < 16; ++it) {
            int idx = tid + it * 256;
            int r = idx >> 5, c0 = (idx & 31) << 2;
            float4 v = x4[idx];
            uint32_t h01 = h2pack(v.x, v.y);
            uint32_t h23 = h2pack(v.z, v.w);
            *(unsigned long long*)&XH[r * LDX + c0] =
                (unsigned long long)h01 | ((unsigned long long)h23 << 32);
        }
    }
    __syncthreads();

    // ================= Phase 1: QKV[128,192] = X[128,128] @ W ================
    // warp owns cols [wid*24, wid*24+24) (3 n-tiles), all 128 rows (8 m-tiles)
    float acc[8][3][4];
    #pragma unroll
    for (int m = 0; m < 8; m++)
        #pragma unroll
        for (int j = 0; j < 3; j++)
            #pragma unroll
            for (int e = 0; e < 4; e++) acc[m][j][e] = 0.f;

    const uint32_t xlmBase = smb + (uint32_t)(lmRow * 272 + lmCol);

    #pragma unroll
    for (int kt = 0; kt < 8; ++kt) {
        uint2 B0 = WFRAG[((wid * 3 + 0) * 8 + kt) * 32 + lane];
        uint2 B1 = WFRAG[((wid * 3 + 1) * 8 + kt) * 32 + lane];
        uint2 B2 = WFRAG[((wid * 3 + 2) * 8 + kt) * 32 + lane];
        #pragma unroll
        for (int m = 0; m < 8; ++m) {
            uint32_t aH = xlmBase + (uint32_t)(m * 16 * 272 + kt * 32);
            uint32_t ah0, ah1, ah2, ah3;
            ldsm4(aH, ah0, ah1, ah2, ah3);
            mma16816(acc[m][0], ah0, ah1, ah2, ah3, B0.x, B0.y);
            mma16816(acc[m][1], ah0, ah1, ah2, ah3, B1.x, B1.y);
            mma16816(acc[m][2], ah0, ah1, ah2, ah3, B2.x, B2.y);
        }
    }
    __syncthreads();   // X reads done before arena overwrite

    // ---- writeback: Q split [t][h]; K single [t][h]; V single transposed [h][t]
    #pragma unroll
    for (int m = 0; m < 8; ++m) {
        int rA = m * 16 + lr;
        int rB = rA + 8;
        int b_ = rA >> 6;
        int tA = rA & 63, tB = rB & 63;
        #pragma unroll
        for (int j = 0; j < 3; ++j) {
            int colbase = wid * 24 + j * 8;
            int rg = colbase >> 6;          // 0=Q 1=K 2=V
            int off = colbase & 63;
            float* a = acc[m][j];
            if (rg == 0) {
                uint32_t* DH = (uint32_t*)(sm + A2OFF(0, b_));
                uint32_t* DL = (uint32_t*)(sm + A2OFF(1, b_));
                int ci = (off >> 1) + qk;
                uint32_t H, L;
                sp2h(a[0], a[1], H, L); DH[tA * 36 + ci] = H; DL[tA * 36 + ci] = L;
                sp2h(a[2], a[3], H, L); DH[tB * 36 + ci] = H; DL[tB * 36 + ci] = L;
            } else if (rg == 1) {
                uint32_t* DK = (uint32_t*)(sm + A2OFF(2, b_));
                int ci = (off >> 1) + qk;
                DK[tA * 36 + ci] = h2pack(a[0], a[1]);
                DK[tB * 36 + ci] = h2pack(a[2], a[3]);
            } else {
                uint16_t* VH = (uint16_t*)(sm + A2OFF(3, b_));
                int h0 = off + qk * 2;
                VH[h0 * LD2 + tA]       = __half_as_ushort(__float2half_rn(a[0]));
                VH[(h0 + 1) * LD2 + tA] = __half_as_ushort(__float2half_rn(a[1]));
                VH[h0 * LD2 + tB]       = __half_as_ushort(__float2half_rn(a[2]));
                VH[(h0 + 1) * LD2 + tB] = __half_as_ushort(__float2half_rn(a[3]));
            }
        }
    }
    __syncthreads();

    // ================= Phase 2: S = Q @ K^T (per batch, in registers) ========
    const int bb2 = wid >> 2;            // batch
    const int mrow = (wid & 3) * 16;     // 16-row block within batch
    const uint32_t* KK32 = (const uint32_t*)(sm + A2OFF(2, bb2));

    float s2[8][4];
    #pragma unroll
    for (int n = 0; n < 8; n++)
        #pragma unroll
        for (int e = 0; e < 4; e++) s2[n][e] = 0.f;

    const uint32_t qlmBase = smb + (uint32_t)(A2OFF(0, bb2) + mrow * 144 + lmRow * 144 + lmCol);

    #pragma unroll
    for (int kt = 0; kt < 4; ++kt) {
        uint32_t aQ = qlmBase + (uint32_t)(kt * 32);
        uint32_t ah0, ah1, ah2, ah3, al0, al1, al2, al3;
        ldsm4(aQ,         ah0, ah1, ah2, ah3);
        ldsm4(aQ + 18432, al0, al1, al2, al3);   // QL plane
        #pragma unroll
        for (int nt = 0; nt < 8; ++nt) {
            int n = nt * 8 + lr;
            int bi = n * 36 + kt * 8 + qk;
            uint32_t bh0 = KK32[bi], bh1 = KK32[bi + 4];
            mma16816(s2[nt], ah0, ah1, ah2, ah3, bh0, bh1);
            mma16816(s2[nt], al0, al1, al2, al3, bh0, bh1);
        }
    }

    // ---- causal softmax in registers ----
    const int rowA = mrow + lr, rowB = rowA + 8;
    {
        float mA = -1e30f, mB = -1e30f;
        #pragma unroll
        for (int nt = 0; nt < 8; ++nt) {
            int c0 = nt * 8 + qk * 2;
            s2[nt][0] = (c0     <= rowA) ? s2[nt][0] : -1e30f;
            s2[nt][1] = (c0 + 1 <= rowA) ? s2[nt][1] : -1e30f;
            s2[nt][2] = (c0     <= rowB) ? s2[nt][2] : -1e30f;
            s2[nt][3] = (c0 + 1 <= rowB) ? s2[nt][3] : -1e30f;
            mA = fmaxf(mA, fmaxf(s2[nt][0], s2[nt][1]));
            mB = fmaxf(mB, fmaxf(s2[nt][2], s2[nt][3]));
        }
        mA = fmaxf(mA, __shfl_xor_sync(0xffffffffu, mA, 1));
        mA = fmaxf(mA, __shfl_xor_sync(0xffffffffu, mA, 2));
        mB = fmaxf(mB, __shfl_xor_sync(0xffffffffu, mB, 1));
        mB = fmaxf(mB, __shfl_xor_sync(0xffffffffu, mB, 2));
        float sA = 0.f, sB = 0.f;
        #pragma unroll
        for (int nt = 0; nt < 8; ++nt) {
            int c0 = nt * 8 + qk * 2;
            float e0 = (c0     <= rowA) ? __expf(s2[nt][0] - mA) : 0.f;
            float e1 = (c0 + 1 <= rowA) ? __expf(s2[nt][1] - mA) : 0.f;
            float e2 = (c0     <= rowB) ? __expf(s2[nt][2] - mB) : 0.f;
            float e3 = (c0 + 1 <= rowB) ? __expf(s2[nt][3] - mB) : 0.f;
            s2[nt][0] = e0; s2[nt][1] = e1; s2[nt][2] = e2; s2[nt][3] = e3;
            sA += e0 + e1;  sB += e2 + e3;
        }
        sA += __shfl_xor_sync(0xffffffffu, sA, 1);
        sA += __shfl_xor_sync(0xffffffffu, sA, 2);
        sB += __shfl_xor_sync(0xffffffffu, sB, 1);
        sB += __shfl_xor_sync(0xffffffffu, sB, 2);
        float iA = __frcp_rn(sA), iB = __frcp_rn(sB);
        #pragma unroll
        for (int nt = 0; nt < 8; ++nt) {
            s2[nt][0] *= iA; s2[nt][1] *= iA;
            s2[nt][2] *= iB; s2[nt][3] *= iB;
        }
    }

    // ================= Phase 3: O = P @ V (A fragments built in-register) ====
    const uint32_t* VV32 = (const uint32_t*)(sm + A2OFF(3, bb2));
    float o[8][4];
    #pragma unroll
    for (int n = 0; n < 8; n++)
        #pragma unroll
        for (int e = 0; e < 4; e++) o[n][e] = 0.f;

    #pragma unroll
    for (int kt = 0; kt < 4; ++kt) {
        uint32_t ah0, ah1, ah2, ah3, al0, al1, al2, al3;
        sp2h(s2[2 * kt][0],     s2[2 * kt][1],     ah0, al0);
        sp2h(s2[2 * kt][2],     s2[2 * kt][3],     ah1, al1);
        sp2h(s2[2 * kt + 1][0], s2[2 * kt + 1][1], ah2, al2);
        sp2h(s2[2 * kt + 1][2], s2[2 * kt + 1][3], ah3, al3);
        #pragma unroll
        for (int nt = 0; nt < 8; ++nt) {
            int n = nt * 8 + lr;
            int bi = n * 36 + kt * 8 + qk;
            uint32_t bh0 = VV32[bi], bh1 = VV32[bi + 4];
            mma16816(o[nt], ah0, ah1, ah2, ah3, bh0, bh1);
            mma16816(o[nt], al0, al1, al2, al3, bh0, bh1);
        }
    }

    // ---- store O ----
    {
        float* ob = out + ((size_t)(b0 + bb2) * TT) * HH;
        #pragma unroll
        for (int nt = 0; nt < 8; ++nt) {
            int c0 = nt * 8 + qk * 2;
            *(float2*)&ob[rowA * HH + c0] = make_float2(o[nt][0], o[nt][1]);
            *(float2*)&ob[rowB * HH + c0] = make_float2(o[nt][2], o[nt][3]);
        }
    }
}

extern "C" void kernel_launch(void* const* d_in, const int* in_sizes, int n_in,
                              void* d_out, int out_size) {
    const float* x  = (const float*)d_in[0];
    const float* Wq = (const float*)d_in[1];
    const float* Wk = (const float*)d_in[2];
    const float* Wv = (const float*)d_in[3];
    float* out = (float*)d_out;

    int B = in_sizes[0] / (TT * CC);

    prep_w_kernel<<<24, 256>>>(Wq, Wk, Wv);

    cudaFuncSetAttribute(DiqqetBashi_hmma5_kernel,
                         cudaFuncAttributeMaxDynamicSharedMemorySize, SMEM_BYTES);
    DiqqetBashi_hmma5_kernel<<<B / 2, 256, SMEM_BYTES>>>(x, out);
}

// round 9
// speedup vs baseline: 5.9698x; 1.0997x over previous
#include <cuda_runtime.h>
#include <cuda_fp16.h>
#include <stdint.h>

#define TT 64
#define CC 128
#define HH 64
#define SCALE_Q 0.08838834764831844f   // 128^-0.5

// W single-fp16 fragment-ordered: [nt(24)][kt(8)][lane(32)] -> {b0,b1}
__device__ uint2 WFRAG[6144];

// ---------------- smem arena (byte offsets) ----------------
// Phase 1: XH [128 x 136 halves] @0 (34816B)  -- aliased by:
// Phase 2/3: arr 0=Q 1=K 2=VT ; each [64 x 72] fp16 per batch (9216 B), 2 batches
#define SMEM_BYTES 55296
#define LDX 136
#define LD2 72
#define A2OFF(arr, b) ((arr) * 18432 + (b) * 9216)

// ---------------- helpers ----------------
__device__ __forceinline__ uint32_t h2pack(float v0, float v1) {
    __half2 h = __floats2half2_rn(v0, v1);
    return *(uint32_t*)&h;
}
// non-volatile — pure register op, let ptxas schedule freely
__device__ __forceinline__ void mma16816(float* c,
                                         uint32_t a0, uint32_t a1, uint32_t a2, uint32_t a3,
                                         uint32_t b0, uint32_t b1) {
    asm("mma.sync.aligned.m16n8k16.row.col.f32.f16.f16.f32 "
        "{%0,%1,%2,%3}, {%4,%5,%6,%7}, {%8,%9}, {%0,%1,%2,%3};"
        : "+f"(c[0]), "+f"(c[1]), "+f"(c[2]), "+f"(c[3])
        : "r"(a0), "r"(a1), "r"(a2), "r"(a3), "r"(b0), "r"(b1));
}
__device__ __forceinline__ void ldsm4(uint32_t addr, uint32_t& r0, uint32_t& r1,
                                      uint32_t& r2, uint32_t& r3) {
    asm("ldmatrix.sync.aligned.m8n8.x4.shared.b16 {%0,%1,%2,%3}, [%4];"
        : "=r"(r0), "=r"(r1), "=r"(r2), "=r"(r3) : "r"(addr) : "memory");
}

// ---------------- prep kernel: W -> fragment-ordered fp16 global ----------------
__global__ void prep_w_kernel(const float* __restrict__ Wq,
                              const float* __restrict__ Wk,
                              const float* __restrict__ Wv) {
    int i = blockIdx.x * 256 + threadIdx.x;
    if (i >= 6144) return;
    int lane = i & 31;
    int kt   = (i >> 5) & 7;
    int nt   = i >> 8;
    int qk = lane & 3, lr = lane >> 2;
    int n = nt * 8 + lr;
    int g = n >> 6, h = n & 63;
    const float* Wg = (g == 0) ? Wq : (g == 1) ? Wk : Wv;
    float s = (g == 0) ? SCALE_Q : 1.0f;
    int k0 = kt * 16 + qk * 2;
    float w0 = Wg[(k0    ) * HH + h] * s;
    float w1 = Wg[(k0 + 1) * HH + h] * s;
    float w2 = Wg[(k0 + 8) * HH + h] * s;
    float w3 = Wg[(k0 + 9) * HH + h] * s;
    WFRAG[i] = make_uint2(h2pack(w0, w1), h2pack(w2, w3));
}

// ---------------- main kernel ----------------
__global__ void __launch_bounds__(256, 2)
DiqqetBashi_hmma6_kernel(const float* __restrict__ x,
                         float* __restrict__ out) {
    extern __shared__ char sm[];
    const int tid  = threadIdx.x;
    const int wid  = tid >> 5;
    const int lane = tid & 31;
    const int qk   = lane & 3;
    const int lr   = lane >> 2;
    const int b0   = blockIdx.x * 2;

    const uint32_t smb = (uint32_t)__cvta_generic_to_shared(sm);
    const int lmRow  = (lane & 7) + ((lane >> 3) & 1) * 8;
    const int lmCol  = (lane >> 4) * 16;
    // B-fragment ldmatrix per-lane offset (row stride 144B, two 16B k-chunks, 2 n-tiles)
    const int bfLane = ((lane >> 4) * 8 + (lane & 7)) * 144 + ((lane >> 3) & 1) * 16;

    uint16_t* XH = (uint16_t*)sm;

    // ---- stage X (2 batches = 128 rows x 128 cols f32) -> single fp16 ----
    {
        const float4* x4 = (const float4*)(x + (size_t)b0 * TT * CC);
        #pragma unroll
        for (int it = 0; it < 16; ++it) {
            int idx = tid + it * 256;
            int r = idx >> 5, c0 = (idx & 31) << 2;
            float4 v = x4[idx];
            uint32_t h01 = h2pack(v.x, v.y);
            uint32_t h23 = h2pack(v.z, v.w);
            *(unsigned long long*)&XH[r * LDX + c0] =
                (unsigned long long)h01 | ((unsigned long long)h23 << 32);
        }
    }
    __syncthreads();

    // ================= Phase 1: QKV[128,192] = X[128,128] @ W ================
    float acc[8][3][4];
    #pragma unroll
    for (int m = 0; m < 8; m++)
        #pragma unroll
        for (int j = 0; j < 3; j++)
            #pragma unroll
            for (int e = 0; e < 4; e++) acc[m][j][e] = 0.f;

    const uint32_t xlmBase = smb + (uint32_t)(lmRow * 272 + lmCol);

    #pragma unroll
    for (int kt = 0; kt < 8; ++kt) {
        uint2 B0 = WFRAG[((wid * 3 + 0) * 8 + kt) * 32 + lane];
        uint2 B1 = WFRAG[((wid * 3 + 1) * 8 + kt) * 32 + lane];
        uint2 B2 = WFRAG[((wid * 3 + 2) * 8 + kt) * 32 + lane];
        #pragma unroll
        for (int m = 0; m < 8; ++m) {
            uint32_t aH = xlmBase + (uint32_t)(m * 16 * 272 + kt * 32);
            uint32_t ah0, ah1, ah2, ah3;
            ldsm4(aH, ah0, ah1, ah2, ah3);
            mma16816(acc[m][0], ah0, ah1, ah2, ah3, B0.x, B0.y);
            mma16816(acc[m][1], ah0, ah1, ah2, ah3, B1.x, B1.y);
            mma16816(acc[m][2], ah0, ah1, ah2, ah3, B2.x, B2.y);
        }
    }
    __syncthreads();   // X reads done before arena overwrite

    // ---- writeback (all single fp16): Q,K [t][h]; V transposed [h][t] ----
    #pragma unroll
    for (int m = 0; m < 8; ++m) {
        int rA = m * 16 + lr;
        int rB = rA + 8;
        int b_ = rA >> 6;
        int tA = rA & 63, tB = rB & 63;
        #pragma unroll
        for (int j = 0; j < 3; ++j) {
            int colbase = wid * 24 + j * 8;
            int rg = colbase >> 6;          // 0=Q 1=K 2=V
            int off = colbase & 63;
            float* a = acc[m][j];
            if (rg < 2) {
                uint32_t* D = (uint32_t*)(sm + A2OFF(rg, b_));
                int ci = (off >> 1) + qk;
                D[tA * 36 + ci] = h2pack(a[0], a[1]);
                D[tB * 36 + ci] = h2pack(a[2], a[3]);
            } else {
                uint16_t* VH = (uint16_t*)(sm + A2OFF(2, b_));
                int h0 = off + qk * 2;
                VH[h0 * LD2 + tA]       = __half_as_ushort(__float2half_rn(a[0]));
                VH[(h0 + 1) * LD2 + tA] = __half_as_ushort(__float2half_rn(a[1]));
                VH[h0 * LD2 + tB]       = __half_as_ushort(__float2half_rn(a[2]));
                VH[(h0 + 1) * LD2 + tB] = __half_as_ushort(__float2half_rn(a[3]));
            }
        }
    }
    __syncthreads();

    // ================= Phase 2: S = Q @ K^T (per batch, in registers) ========
    const int bb2 = wid >> 2;            // batch
    const int mrow = (wid & 3) * 16;     // 16-row block within batch

    float s2[8][4];
    #pragma unroll
    for (int n = 0; n < 8; n++)
        #pragma unroll
        for (int e = 0; e < 4; e++) s2[n][e] = 0.f;

    const uint32_t qlmBase = smb + (uint32_t)(A2OFF(0, bb2) + mrow * 144 + lmRow * 144 + lmCol);
    const uint32_t kfBase  = smb + (uint32_t)(A2OFF(1, bb2) + bfLane);

    #pragma unroll
    for (int kt = 0; kt < 4; ++kt) {
        uint32_t ah0, ah1, ah2, ah3;
        ldsm4(qlmBase + (uint32_t)(kt * 32), ah0, ah1, ah2, ah3);
        #pragma unroll
        for (int ntp = 0; ntp < 4; ++ntp) {
            uint32_t b00, b01, b10, b11;
            ldsm4(kfBase + (uint32_t)(ntp * 2304 + kt * 32), b00, b01, b10, b11);
            mma16816(s2[2 * ntp],     ah0, ah1, ah2, ah3, b00, b01);
            mma16816(s2[2 * ntp + 1], ah0, ah1, ah2, ah3, b10, b11);
        }
    }

    // ---- causal softmax in registers ----
    const int rowA = mrow + lr, rowB = rowA + 8;
    {
        float mA = -1e30f, mB = -1e30f;
        #pragma unroll
        for (int nt = 0; nt < 8; ++nt) {
            int c0 = nt * 8 + qk * 2;
            s2[nt][0] = (c0     <= rowA) ? s2[nt][0] : -1e30f;
            s2[nt][1] = (c0 + 1 <= rowA) ? s2[nt][1] : -1e30f;
            s2[nt][2] = (c0     <= rowB) ? s2[nt][2] : -1e30f;
            s2[nt][3] = (c0 + 1 <= rowB) ? s2[nt][3] : -1e30f;
            mA = fmaxf(mA, fmaxf(s2[nt][0], s2[nt][1]));
            mB = fmaxf(mB, fmaxf(s2[nt][2], s2[nt][3]));
        }
        mA = fmaxf(mA, __shfl_xor_sync(0xffffffffu, mA, 1));
        mA = fmaxf(mA, __shfl_xor_sync(0xffffffffu, mA, 2));
        mB = fmaxf(mB, __shfl_xor_sync(0xffffffffu, mB, 1));
        mB = fmaxf(mB, __shfl_xor_sync(0xffffffffu, mB, 2));
        float sA = 0.f, sB = 0.f;
        #pragma unroll
        for (int nt = 0; nt < 8; ++nt) {
            int c0 = nt * 8 + qk * 2;
            float e0 = (c0     <= rowA) ? __expf(s2[nt][0] - mA) : 0.f;
            float e1 = (c0 + 1 <= rowA) ? __expf(s2[nt][1] - mA) : 0.f;
            float e2 = (c0     <= rowB) ? __expf(s2[nt][2] - mB) : 0.f;
            float e3 = (c0 + 1 <= rowB) ? __expf(s2[nt][3] - mB) : 0.f;
            s2[nt][0] = e0; s2[nt][1] = e1; s2[nt][2] = e2; s2[nt][3] = e3;
            sA += e0 + e1;  sB += e2 + e3;
        }
        sA += __shfl_xor_sync(0xffffffffu, sA, 1);
        sA += __shfl_xor_sync(0xffffffffu, sA, 2);
        sB += __shfl_xor_sync(0xffffffffu, sB, 1);
        sB += __shfl_xor_sync(0xffffffffu, sB, 2);
        float iA = __frcp_rn(sA), iB = __frcp_rn(sB);
        #pragma unroll
        for (int nt = 0; nt < 8; ++nt) {
            s2[nt][0] *= iA; s2[nt][1] *= iA;
            s2[nt][2] *= iB; s2[nt][3] *= iB;
        }
    }

    // ================= Phase 3: O = P @ V (P single fp16, in-register) ======
    const uint32_t vfBase = smb + (uint32_t)(A2OFF(2, bb2) + bfLane);
    float o[8][4];
    #pragma unroll
    for (int n = 0; n < 8; n++)
        #pragma unroll
        for (int e = 0; e < 4; e++) o[n][e] = 0.f;

    #pragma unroll
    for (int kt = 0; kt < 4; ++kt) {
        uint32_t ah0 = h2pack(s2[2 * kt][0],     s2[2 * kt][1]);
        uint32_t ah1 = h2pack(s2[2 * kt][2],     s2[2 * kt][3]);
        uint32_t ah2 = h2pack(s2[2 * kt + 1][0], s2[2 * kt + 1][1]);
        uint32_t ah3 = h2pack(s2[2 * kt + 1][2], s2[2 * kt + 1][3]);
        #pragma unroll
        for (int ntp = 0; ntp < 4; ++ntp) {
            uint32_t b00, b01, b10, b11;
            ldsm4(vfBase + (uint32_t)(ntp * 2304 + kt * 32), b00, b01, b10, b11);
            mma16816(o[2 * ntp],     ah0, ah1, ah2, ah3, b00, b01);
            mma16816(o[2 * ntp + 1], ah0, ah1, ah2, ah3, b10, b11);
        }
    }

    // ---- store O ----
    {
        float* ob = out + ((size_t)(b0 + bb2) * TT) * HH;
        #pragma unroll
        for (int nt = 0; nt < 8; ++nt) {
            int c0 = nt * 8 + qk * 2;
            *(float2*)&ob[rowA * HH + c0] = make_float2(o[nt][0], o[nt][1]);
            *(float2*)&ob[rowB * HH + c0] = make_float2(o[nt][2], o[nt][3]);
        }
    }
}

extern "C" void kernel_launch(void* const* d_in, const int* in_sizes, int n_in,
                              void* d_out, int out_size) {
    const float* x  = (const float*)d_in[0];
    const float* Wq = (const float*)d_in[1];
    const float* Wk = (const float*)d_in[2];
    const float* Wv = (const float*)d_in[3];
    float* out = (float*)d_out;

    int B = in_sizes[0] / (TT * CC);

    prep_w_kernel<<<24, 256>>>(Wq, Wk, Wv);

    cudaFuncSetAttribute(DiqqetBashi_hmma6_kernel,
                         cudaFuncAttributeMaxDynamicSharedMemorySize, SMEM_BYTES);
    DiqqetBashi_hmma6_kernel<<<B / 2, 256, SMEM_BYTES>>>(x, out);
}

// round 10
// speedup vs baseline: 6.2803x; 1.0520x over previous
#include <cuda_runtime.h>
#include <cuda_fp16.h>
#include <stdint.h>

#define TT 64
#define CC 128
#define HH 64
#define SCALE_Q 0.08838834764831844f   // 128^-0.5

// W single-fp16 fragment-ordered: [nt(24)][kt(8)][lane(32)] -> {b0,b1}
__device__ uint2 WFRAG[6144];

// ---------------- smem layout (byte offsets), NO aliasing ----------------
// XH [128 rows x 136 halves] @0 (34816 B)
// arena @34816: arr 0=Q 1=K 2=V, each [64 x 72] fp16 per batch (9216 B), 2 batches
#define XH0 0
#define AR(arr, b) (34816 + (arr) * 18432 + (b) * 9216)
#define SMEM_BYTES 90112
#define LDX 136

// ---------------- helpers ----------------
__device__ __forceinline__ uint32_t h2pack(float v0, float v1) {
    __half2 h = __floats2half2_rn(v0, v1);
    return *(uint32_t*)&h;
}
__device__ __forceinline__ void mma16816(float* c,
                                         uint32_t a0, uint32_t a1, uint32_t a2, uint32_t a3,
                                         uint32_t b0, uint32_t b1) {
    asm("mma.sync.aligned.m16n8k16.row.col.f32.f16.f16.f32 "
        "{%0,%1,%2,%3}, {%4,%5,%6,%7}, {%8,%9}, {%0,%1,%2,%3};"
        : "+f"(c[0]), "+f"(c[1]), "+f"(c[2]), "+f"(c[3])
        : "r"(a0), "r"(a1), "r"(a2), "r"(a3), "r"(b0), "r"(b1));
}
__device__ __forceinline__ void ldsm4(uint32_t addr, uint32_t& r0, uint32_t& r1,
                                      uint32_t& r2, uint32_t& r3) {
    asm("ldmatrix.sync.aligned.m8n8.x4.shared.b16 {%0,%1,%2,%3}, [%4];"
        : "=r"(r0), "=r"(r1), "=r"(r2), "=r"(r3) : "r"(addr) : "memory");
}
__device__ __forceinline__ void ldsm4t(uint32_t addr, uint32_t& r0, uint32_t& r1,
                                       uint32_t& r2, uint32_t& r3) {
    asm("ldmatrix.sync.aligned.m8n8.x4.trans.shared.b16 {%0,%1,%2,%3}, [%4];"
        : "=r"(r0), "=r"(r1), "=r"(r2), "=r"(r3) : "r"(addr) : "memory");
}

// ---------------- prep kernel: W -> fragment-ordered fp16 global ----------------
__global__ void prep_w_kernel(const float* __restrict__ Wq,
                              const float* __restrict__ Wk,
                              const float* __restrict__ Wv) {
    int i = blockIdx.x * 256 + threadIdx.x;
    if (i >= 6144) return;
    int lane = i & 31;
    int kt   = (i >> 5) & 7;
    int nt   = i >> 8;
    int qk = lane & 3, lr = lane >> 2;
    int n = nt * 8 + lr;
    int g = n >> 6, h = n & 63;
    const float* Wg = (g == 0) ? Wq : (g == 1) ? Wk : Wv;
    float s = (g == 0) ? SCALE_Q : 1.0f;
    int k0 = kt * 16 + qk * 2;
    float w0 = Wg[(k0    ) * HH + h] * s;
    float w1 = Wg[(k0 + 1) * HH + h] * s;
    float w2 = Wg[(k0 + 8) * HH + h] * s;
    float w3 = Wg[(k0 + 9) * HH + h] * s;
    WFRAG[i] = make_uint2(h2pack(w0, w1), h2pack(w2, w3));
}

// ---------------- main kernel ----------------
__global__ void __launch_bounds__(256, 2)
DiqqetBashi_hmma7_kernel(const float* __restrict__ x,
                         float* __restrict__ out) {
    extern __shared__ char sm[];
    const int tid  = threadIdx.x;
    const int wid  = tid >> 5;
    const int lane = tid & 31;
    const int qk   = lane & 3;
    const int lr   = lane >> 2;
    const int b0   = blockIdx.x * 2;

    const uint32_t smb = (uint32_t)__cvta_generic_to_shared(sm);
    const int lmRow  = (lane & 7) + ((lane >> 3) & 1) * 8;
    const int lmCol  = (lane >> 4) * 16;
    // K B-fragment lane offset (non-trans): rows = n, 144 B stride
    const int bfLane = ((lane >> 4) * 8 + (lane & 7)) * 144 + ((lane >> 3) & 1) * 16;
    // V B-fragment lane offset (trans): matrices over stored V[t][h]
    const int vfLane = ((((lane >> 3) & 1) * 8) + (lane & 7)) * 144 + (lane >> 4) * 16;

    // ---- hoist all W B-fragments (latency overlaps X staging) ----
    uint2 Bw[3][8];
    #pragma unroll
    for (int j = 0; j < 3; ++j)
        #pragma unroll
        for (int kt = 0; kt < 8; ++kt)
            Bw[j][kt] = WFRAG[((wid * 3 + j) * 8 + kt) * 32 + lane];

    uint16_t* XH = (uint16_t*)sm;

    // ---- stage X (2 batches = 128 rows x 128 cols f32) -> single fp16 ----
    {
        const float4* x4 = (const float4*)(x + (size_t)b0 * TT * CC);
        #pragma unroll
        for (int it = 0; it < 16; ++it) {
            int idx = tid + it * 256;
            int r = idx >> 5, c0 = (idx & 31) << 2;
            float4 v = x4[idx];
            uint32_t h01 = h2pack(v.x, v.y);
            uint32_t h23 = h2pack(v.z, v.w);
            *(unsigned long long*)&XH[r * LDX + c0] =
                (unsigned long long)h01 | ((unsigned long long)h23 << 32);
        }
    }
    __syncthreads();

    // ================= Phase 1: QKV[128,192] = X[128,128] @ W ================
    // m-outer: small acc live range; writeback interleaves with next m's MMAs.
    const uint32_t xlmBase = smb + (uint32_t)(lmRow * 272 + lmCol);
    const int colb0 = wid * 24;

    #pragma unroll
    for (int m = 0; m < 8; ++m) {
        float a0v[4] = {0.f, 0.f, 0.f, 0.f};
        float a1v[4] = {0.f, 0.f, 0.f, 0.f};
        float a2v[4] = {0.f, 0.f, 0.f, 0.f};
        #pragma unroll
        for (int kt = 0; kt < 8; ++kt) {
            uint32_t f0, f1, f2, f3;
            ldsm4(xlmBase + (uint32_t)(m * 16 * 272 + kt * 32), f0, f1, f2, f3);
            mma16816(a0v, f0, f1, f2, f3, Bw[0][kt].x, Bw[0][kt].y);
            mma16816(a1v, f0, f1, f2, f3, Bw[1][kt].x, Bw[1][kt].y);
            mma16816(a2v, f0, f1, f2, f3, Bw[2][kt].x, Bw[2][kt].y);
        }
        // writeback tile m (uniform: Q, K, V all stored [t][h])
        int rA = m * 16 + lr;
        int rB = rA + 8;
        int b_ = rA >> 6;
        int tA = rA & 63, tB = rB & 63;
        float* accs[3] = {a0v, a1v, a2v};
        #pragma unroll
        for (int j = 0; j < 3; ++j) {
            int colbase = colb0 + j * 8;
            int rg = colbase >> 6;          // 0=Q 1=K 2=V
            int ci = ((colbase & 63) >> 1) + qk;
            uint32_t* D = (uint32_t*)(sm + AR(rg, b_));
            D[tA * 36 + ci] = h2pack(accs[j][0], accs[j][1]);
            D[tB * 36 + ci] = h2pack(accs[j][2], accs[j][3]);
        }
    }
    __syncthreads();

    // ================= Phase 2: S = Q @ K^T (per batch, in registers) ========
    const int bb2 = wid >> 2;            // batch
    const int mrow = (wid & 3) * 16;     // 16-row block within batch

    float s2[8][4];
    #pragma unroll
    for (int n = 0; n < 8; n++)
        #pragma unroll
        for (int e = 0; e < 4; e++) s2[n][e] = 0.f;

    const uint32_t qlmBase = smb + (uint32_t)(AR(0, bb2) + mrow * 144 + lmRow * 144 + lmCol);
    const uint32_t kfBase  = smb + (uint32_t)(AR(1, bb2) + bfLane);

    #pragma unroll
    for (int kt = 0; kt < 4; ++kt) {
        uint32_t ah0, ah1, ah2, ah3;
        ldsm4(qlmBase + (uint32_t)(kt * 32), ah0, ah1, ah2, ah3);
        #pragma unroll
        for (int ntp = 0; ntp < 4; ++ntp) {
            uint32_t b00, b01, b10, b11;
            ldsm4(kfBase + (uint32_t)(ntp * 2304 + kt * 32), b00, b01, b10, b11);
            mma16816(s2[2 * ntp],     ah0, ah1, ah2, ah3, b00, b01);
            mma16816(s2[2 * ntp + 1], ah0, ah1, ah2, ah3, b10, b11);
        }
    }

    // ---- causal softmax in registers ----
    const int rowA = mrow + lr, rowB = rowA + 8;
    {
        float mA = -1e30f, mB = -1e30f;
        #pragma unroll
        for (int nt = 0; nt < 8; ++nt) {
            int c0 = nt * 8 + qk * 2;
            s2[nt][0] = (c0     <= rowA) ? s2[nt][0] : -1e30f;
            s2[nt][1] = (c0 + 1 <= rowA) ? s2[nt][1] : -1e30f;
            s2[nt][2] = (c0     <= rowB) ? s2[nt][2] : -1e30f;
            s2[nt][3] = (c0 + 1 <= rowB) ? s2[nt][3] : -1e30f;
            mA = fmaxf(mA, fmaxf(s2[nt][0], s2[nt][1]));
            mB = fmaxf(mB, fmaxf(s2[nt][2], s2[nt][3]));
        }
        mA = fmaxf(mA, __shfl_xor_sync(0xffffffffu, mA, 1));
        mA = fmaxf(mA, __shfl_xor_sync(0xffffffffu, mA, 2));
        mB = fmaxf(mB, __shfl_xor_sync(0xffffffffu, mB, 1));
        mB = fmaxf(mB, __shfl_xor_sync(0xffffffffu, mB, 2));
        float sA = 0.f, sB = 0.f;
        #pragma unroll
        for (int nt = 0; nt < 8; ++nt) {
            int c0 = nt * 8 + qk * 2;
            float e0 = (c0     <= rowA) ? __expf(s2[nt][0] - mA) : 0.f;
            float e1 = (c0 + 1 <= rowA) ? __expf(s2[nt][1] - mA) : 0.f;
            float e2 = (c0     <= rowB) ? __expf(s2[nt][2] - mB) : 0.f;
            float e3 = (c0 + 1 <= rowB) ? __expf(s2[nt][3] - mB) : 0.f;
            s2[nt][0] = e0; s2[nt][1] = e1; s2[nt][2] = e2; s2[nt][3] = e3;
            sA += e0 + e1;  sB += e2 + e3;
        }
        sA += __shfl_xor_sync(0xffffffffu, sA, 1);
        sA += __shfl_xor_sync(0xffffffffu, sA, 2);
        sB += __shfl_xor_sync(0xffffffffu, sB, 1);
        sB += __shfl_xor_sync(0xffffffffu, sB, 2);
        float iA = __frcp_rn(sA), iB = __frcp_rn(sB);
        #pragma unroll
        for (int nt = 0; nt < 8; ++nt) {
            s2[nt][0] *= iA; s2[nt][1] *= iA;
            s2[nt][2] *= iB; s2[nt][3] *= iB;
        }
    }

    // ================= Phase 3: O = P @ V (V via ldmatrix.trans) =============
    const uint32_t vfBase = smb + (uint32_t)(AR(2, bb2) + vfLane);
    float o[8][4];
    #pragma unroll
    for (int n = 0; n < 8; n++)
        #pragma unroll
        for (int e = 0; e < 4; e++) o[n][e] = 0.f;

    #pragma unroll
    for (int kt = 0; kt < 4; ++kt) {
        uint32_t ah0 = h2pack(s2[2 * kt][0],     s2[2 * kt][1]);
        uint32_t ah1 = h2pack(s2[2 * kt][2],     s2[2 * kt][3]);
        uint32_t ah2 = h2pack(s2[2 * kt + 1][0], s2[2 * kt + 1][1]);
        uint32_t ah3 = h2pack(s2[2 * kt + 1][2], s2[2 * kt + 1][3]);
        #pragma unroll
        for (int ntp = 0; ntp < 4; ++ntp) {
            uint32_t b00, b01, b10, b11;
            ldsm4t(vfBase + (uint32_t)(kt * 2304 + ntp * 32), b00, b01, b10, b11);
            mma16816(o[2 * ntp],     ah0, ah1, ah2, ah3, b00, b01);
            mma16816(o[2 * ntp + 1], ah0, ah1, ah2, ah3, b10, b11);
        }
    }

    // ---- store O ----
    {
        float* ob = out + ((size_t)(b0 + bb2) * TT) * HH;
        #pragma unroll
        for (int nt = 0; nt < 8; ++nt) {
            int c0 = nt * 8 + qk * 2;
            *(float2*)&ob[rowA * HH + c0] = make_float2(o[nt][0], o[nt][1]);
            *(float2*)&ob[rowB * HH + c0] = make_float2(o[nt][2], o[nt][3]);
        }
    }
}

extern "C" void kernel_launch(void* const* d_in, const int* in_sizes, int n_in,
                              void* d_out, int out_size) {
    const float* x  = (const float*)d_in[0];
    const float* Wq = (const float*)d_in[1];
    const float* Wk = (const float*)d_in[2];
    const float* Wv = (const float*)d_in[3];
    float* out = (float*)d_out;

    int B = in_sizes[0] / (TT * CC);

    prep_w_kernel<<<24, 256>>>(Wq, Wk, Wv);

    cudaFuncSetAttribute(DiqqetBashi_hmma7_kernel,
                         cudaFuncAttributeMaxDynamicSharedMemorySize, SMEM_BYTES);
    DiqqetBashi_hmma7_kernel<<<B / 2, 256, SMEM_BYTES>>>(x, out);
}